// round 1
// baseline (speedup 1.0000x reference)
#include <cuda_runtime.h>
#include <cuda_fp16.h>
#include <cstdint>

// Problem dims (fixed by the dataset)
#define T_STEPS 512
#define BATCH   1024
#define DIM     128
#define HID     128
#define G4      512        // 4*HID
#define FUT     128
#define ROWS_PER_BLK 8
#define NBLK    (BATCH / ROWS_PER_BLK)   // 128

// ---------------------------------------------------------------------------
// Device scratch (allocation-free rule: static __device__ globals)
// ---------------------------------------------------------------------------
__device__ float  g_gx[(size_t)T_STEPS * BATCH * G4];   // 1 GB: precomputed x-gates (+bias)
__device__ __half g_whh_h[G4 * HID];                    // fp16 W_hh
__device__ __half g_weff_h[G4 * HID];                   // fp16 W_eff = W_hh + W_ih@W_lin
__device__ float  g_beff[G4];                           // b_eff = b_ih+b_hh + W_ih@b_lin

// ---------------------------------------------------------------------------
// packed f32x2 helpers (sm_103a)
// ---------------------------------------------------------------------------
__device__ __forceinline__ unsigned long long pack2(float x, float y) {
    unsigned long long r;
    asm("mov.b64 %0, {%1, %2};" : "=l"(r) : "f"(x), "f"(y));
    return r;
}
__device__ __forceinline__ void unpack2(unsigned long long v, float& x, float& y) {
    asm("mov.b64 {%0, %1}, %2;" : "=f"(x), "=f"(y) : "l"(v));
}
__device__ __forceinline__ void fma2(unsigned long long& d, unsigned long long a,
                                     unsigned long long b) {
    asm("fma.rn.f32x2 %0, %1, %2, %0;" : "+l"(d) : "l"(a), "l"(b));
}

__device__ __forceinline__ float sigf(float x) {
    return 1.0f / (1.0f + __expf(-x));
}
__device__ __forceinline__ float tanhfast(float x) {
    float ax = fabsf(x);
    float e  = __expf(-2.0f * ax);
    float r  = (1.0f - e) / (1.0f + e);
    return copysignf(r, x);
}

// ---------------------------------------------------------------------------
// Setup: W_eff, b_eff, fp16 copies.  65536 threads.
// ---------------------------------------------------------------------------
__global__ void setup_kernel(const float* __restrict__ W_ih,
                             const float* __restrict__ W_hh,
                             const float* __restrict__ b_ih,
                             const float* __restrict__ b_hh,
                             const float* __restrict__ W_lin,
                             const float* __restrict__ b_lin) {
    int idx = blockIdx.x * blockDim.x + threadIdx.x;   // 0 .. 65535
    int g = idx >> 7;
    int k = idx & 127;
    // W_eff[g][k] = W_hh[g][k] + sum_j W_ih[g][j] * W_lin[j][k]
    float s = W_hh[g * HID + k];
    #pragma unroll 8
    for (int j = 0; j < DIM; j++)
        s = fmaf(W_ih[g * DIM + j], W_lin[j * HID + k], s);
    g_weff_h[idx] = __float2half(s);
    g_whh_h[idx]  = __float2half(W_hh[idx]);
    if (idx < G4) {
        float b = b_ih[idx] + b_hh[idx];
        #pragma unroll 8
        for (int j = 0; j < DIM; j++)
            b = fmaf(W_ih[idx * DIM + j], b_lin[j], b);
        g_beff[idx] = b;
    }
}

// ---------------------------------------------------------------------------
// xgemm: G_x = inp @ W_ih^T + (b_ih + b_hh)
//   A [M=524288, K=128] row-major, W [512, 128] row-major, C [M, 512]
//   128x128 tile / CTA, 256 threads, 8x8 micro-tile, packed fma.rn.f32x2
// ---------------------------------------------------------------------------
#define XGEMM_SMEM ((128 * 64 + 64 * 130) * 4)

__global__ void __launch_bounds__(256)
xgemm_kernel(const float* __restrict__ A, const float* __restrict__ W,
             const float* __restrict__ b_ih, const float* __restrict__ b_hh) {
    extern __shared__ float sm[];
    float* Asub = sm;                 // [128][64]
    float* Bsub = sm + 128 * 64;      // [64][130]  (transposed: [k][n])

    const int tid = threadIdx.x;
    const int tx  = tid & 15;          // n dimension
    const int ty  = tid >> 4;          // m dimension
    const size_t m0 = (size_t)blockIdx.x * 128;
    const int    n0 = blockIdx.y * 128;

    unsigned long long acc[8][4];
    #pragma unroll
    for (int i = 0; i < 8; i++)
        #pragma unroll
        for (int j = 0; j < 4; j++) acc[i][j] = 0ULL;

    for (int kc = 0; kc < 2; kc++) {
        const int k0 = kc * 64;
        // load A chunk [128 m][64 k], coalesced float4
        #pragma unroll
        for (int j = 0; j < 8; j++) {
            int idx = tid + j * 256;
            int m   = idx >> 4;
            int kf  = idx & 15;
            float4 v = *(const float4*)(A + (m0 + m) * 128 + k0 + kf * 4);
            *(float4*)(Asub + m * 64 + kf * 4) = v;
        }
        // load B chunk transposed into [k][n]
        #pragma unroll
        for (int j = 0; j < 8; j++) {
            int idx = tid + j * 256;
            int n   = idx >> 4;
            int kf  = idx & 15;
            float4 v = *(const float4*)(W + (size_t)(n0 + n) * 128 + k0 + kf * 4);
            Bsub[(kf * 4 + 0) * 130 + n] = v.x;
            Bsub[(kf * 4 + 1) * 130 + n] = v.y;
            Bsub[(kf * 4 + 2) * 130 + n] = v.z;
            Bsub[(kf * 4 + 3) * 130 + n] = v.w;
        }
        __syncthreads();

        #pragma unroll 4
        for (int k = 0; k < 64; k++) {
            unsigned long long a2[8];
            #pragma unroll
            for (int i = 0; i < 8; i++) {
                float a = Asub[(ty * 8 + i) * 64 + k];
                a2[i] = pack2(a, a);
            }
            unsigned long long b2[4];
            #pragma unroll
            for (int j = 0; j < 4; j++) {
                float2 bb = *(const float2*)(Bsub + k * 130 + tx * 2 + j * 32);
                b2[j] = pack2(bb.x, bb.y);
            }
            #pragma unroll
            for (int i = 0; i < 8; i++)
                #pragma unroll
                for (int j = 0; j < 4; j++)
                    fma2(acc[i][j], a2[i], b2[j]);
        }
        __syncthreads();
    }

    // epilogue: + bias, store to g_gx
    float2 bias[4];
    #pragma unroll
    for (int j = 0; j < 4; j++) {
        int n = n0 + tx * 2 + j * 32;
        bias[j].x = b_ih[n] + b_hh[n];
        bias[j].y = b_ih[n + 1] + b_hh[n + 1];
    }
    #pragma unroll
    for (int i = 0; i < 8; i++) {
        size_t m = m0 + ty * 8 + i;
        #pragma unroll
        for (int j = 0; j < 4; j++) {
            float x, y;
            unpack2(acc[i][j], x, y);
            float2 o;
            o.x = x + bias[j].x;
            o.y = y + bias[j].y;
            *(float2*)(g_gx + m * G4 + n0 + tx * 2 + j * 32) = o;
        }
    }
}

// ---------------------------------------------------------------------------
// Persistent LSTM recurrence.  128 CTAs x 512 threads; 8 batch rows / CTA.
// Thread (u = tid&127, rg = tid>>7) owns unit u, rows {2rg, 2rg+1}:
//   computes all 4 gates (i,f,g,o) of that unit -> c stays in registers.
// smem: wg  [512][65] half2 (fp16 W_hh, later W_eff)     133120 B
//       wlf [128][130] float (fp32 W_lin)                 66560 B
//       hbuf[128][9]  float (h, [unit][row], padded)       4608 B
// ---------------------------------------------------------------------------
#define LSTM_SMEM (512 * 65 * 4 + 128 * 130 * 4 + 128 * 9 * 4)

__device__ __forceinline__ void linout(const float* __restrict__ wlf,
                                       const float* __restrict__ hbuf,
                                       int u, int r0, float blin,
                                       float& o0, float& o1) {
    float a0 = blin, a1 = blin;
    #pragma unroll 8
    for (int kk = 0; kk < 64; kk++) {
        float2 w  = *(const float2*)(wlf + u * 130 + 2 * kk);
        float h00 = hbuf[(2 * kk) * 9 + r0];
        float h01 = hbuf[(2 * kk) * 9 + r0 + 1];
        float h10 = hbuf[(2 * kk + 1) * 9 + r0];
        float h11 = hbuf[(2 * kk + 1) * 9 + r0 + 1];
        a0 = fmaf(w.x, h00, a0);
        a0 = fmaf(w.y, h10, a0);
        a1 = fmaf(w.x, h01, a1);
        a1 = fmaf(w.y, h11, a1);
    }
    o0 = a0;
    o1 = a1;
}

__global__ void __launch_bounds__(512, 1)
lstm_kernel(const float* __restrict__ W_lin, const float* __restrict__ b_lin,
            float* __restrict__ out) {
    extern __shared__ char smem[];
    __half2* wg   = (__half2*)smem;                                    // [512][65]
    float*   wlf  = (float*)(smem + 512 * 65 * 4);                     // [128][130]
    float*   hbuf = (float*)(smem + 512 * 65 * 4 + 128 * 130 * 4);     // [128][9]

    const int tid = threadIdx.x;
    const int u   = tid & 127;     // unit
    const int rg  = tid >> 7;      // 0..3
    const int r0  = 2 * rg;        // local row pair
    const int blk_row = blockIdx.x * ROWS_PER_BLK;

    // load fp16 W_hh into smem (coalesced)
    const __half2* whh2 = (const __half2*)g_whh_h;
    for (int i = tid; i < G4 * 64; i += 512) {
        int g = i >> 6, kk = i & 63;
        wg[g * 65 + kk] = whh2[i];
    }
    // fp32 W_lin
    for (int i = tid; i < HID * HID; i += 512) {
        int uu = i >> 7, k = i & 127;
        wlf[uu * 130 + k] = W_lin[i];
    }
    for (int i = tid; i < 128 * 9; i += 512) hbuf[i] = 0.0f;
    float c0 = 0.0f, c1 = 0.0f;
    const float blin = b_lin[u];
    __syncthreads();

    // prefetch G_x for t = 0
    float gxv[4][2];
    {
        const float* gxp = g_gx + ((size_t)blk_row + r0) * G4 + u;
        #pragma unroll
        for (int q = 0; q < 4; q++) {
            gxv[q][0] = gxp[q * 128];
            gxv[q][1] = gxp[G4 + q * 128];
        }
    }

    // ---------------- main scan over T ----------------
    for (int t = 0; t < T_STEPS; t++) {
        float acc[4][2];
        #pragma unroll
        for (int q = 0; q < 4; q++) {
            acc[q][0] = gxv[q][0];
            acc[q][1] = gxv[q][1];
        }
        // prefetch next step's G_x (hidden under the k-loop)
        if (t + 1 < T_STEPS) {
            const float* gxp = g_gx + ((size_t)(t + 1) * BATCH + blk_row + r0) * G4 + u;
            #pragma unroll
            for (int q = 0; q < 4; q++) {
                gxv[q][0] = gxp[q * 128];
                gxv[q][1] = gxp[G4 + q * 128];
            }
        }

        #pragma unroll 8
        for (int kk = 0; kk < 64; kk++) {
            float h00 = hbuf[(2 * kk) * 9 + r0];
            float h01 = hbuf[(2 * kk) * 9 + r0 + 1];
            float h10 = hbuf[(2 * kk + 1) * 9 + r0];
            float h11 = hbuf[(2 * kk + 1) * 9 + r0 + 1];
            #pragma unroll
            for (int q = 0; q < 4; q++) {
                float2 w = __half22float2(wg[(u + q * 128) * 65 + kk]);
                acc[q][0] = fmaf(w.x, h00, acc[q][0]);
                acc[q][0] = fmaf(w.y, h10, acc[q][0]);
                acc[q][1] = fmaf(w.x, h01, acc[q][1]);
                acc[q][1] = fmaf(w.y, h11, acc[q][1]);
            }
        }

        // gate activations + state update (PyTorch order i,f,g,o)
        float ig0 = sigf(acc[0][0]), fg0 = sigf(acc[1][0]);
        float gg0 = tanhfast(acc[2][0]), og0 = sigf(acc[3][0]);
        c0 = fmaf(fg0, c0, ig0 * gg0);
        float hn0 = og0 * tanhfast(c0);

        float ig1 = sigf(acc[0][1]), fg1 = sigf(acc[1][1]);
        float gg1 = tanhfast(acc[2][1]), og1 = sigf(acc[3][1]);
        c1 = fmaf(fg1, c1, ig1 * gg1);
        float hn1 = og1 * tanhfast(c1);

        __syncthreads();                 // all reads of old h done
        hbuf[u * 9 + r0]     = hn0;
        hbuf[u * 9 + r0 + 1] = hn1;
        __syncthreads();                 // new h visible
    }

    // ---------------- out[0] = W_lin h_T + b_lin ----------------
    {
        float o0, o1;
        linout(wlf, hbuf, u, r0, blin, o0, o1);
        out[(size_t)(blk_row + r0) * HID + u]     = o0;
        out[(size_t)(blk_row + r0 + 1) * HID + u] = o1;
    }

    // swap in W_eff (gates = W_eff h + b_eff)
    const __half2* weff2 = (const __half2*)g_weff_h;
    for (int i = tid; i < G4 * 64; i += 512) {
        int g = i >> 6, kk = i & 63;
        wg[g * 65 + kk] = weff2[i];
    }
    float beff[4];
    #pragma unroll
    for (int q = 0; q < 4; q++) beff[q] = g_beff[u + q * 128];
    __syncthreads();

    // ---------------- future steps ----------------
    for (int ft = 0; ft < FUT; ft++) {
        float acc[4][2];
        #pragma unroll
        for (int q = 0; q < 4; q++) {
            acc[q][0] = beff[q];
            acc[q][1] = beff[q];
        }
        #pragma unroll 8
        for (int kk = 0; kk < 64; kk++) {
            float h00 = hbuf[(2 * kk) * 9 + r0];
            float h01 = hbuf[(2 * kk) * 9 + r0 + 1];
            float h10 = hbuf[(2 * kk + 1) * 9 + r0];
            float h11 = hbuf[(2 * kk + 1) * 9 + r0 + 1];
            #pragma unroll
            for (int q = 0; q < 4; q++) {
                float2 w = __half22float2(wg[(u + q * 128) * 65 + kk]);
                acc[q][0] = fmaf(w.x, h00, acc[q][0]);
                acc[q][0] = fmaf(w.y, h10, acc[q][0]);
                acc[q][1] = fmaf(w.x, h01, acc[q][1]);
                acc[q][1] = fmaf(w.y, h11, acc[q][1]);
            }
        }

        float ig0 = sigf(acc[0][0]), fg0 = sigf(acc[1][0]);
        float gg0 = tanhfast(acc[2][0]), og0 = sigf(acc[3][0]);
        c0 = fmaf(fg0, c0, ig0 * gg0);
        float hn0 = og0 * tanhfast(c0);

        float ig1 = sigf(acc[0][1]), fg1 = sigf(acc[1][1]);
        float gg1 = tanhfast(acc[2][1]), og1 = sigf(acc[3][1]);
        c1 = fmaf(fg1, c1, ig1 * gg1);
        float hn1 = og1 * tanhfast(c1);

        __syncthreads();
        hbuf[u * 9 + r0]     = hn0;
        hbuf[u * 9 + r0 + 1] = hn1;
        __syncthreads();

        float o0, o1;
        linout(wlf, hbuf, u, r0, blin, o0, o1);
        float* op = out + (size_t)(1 + ft) * BATCH * HID;
        op[(size_t)(blk_row + r0) * HID + u]     = o0;
        op[(size_t)(blk_row + r0 + 1) * HID + u] = o1;
    }
}

// ---------------------------------------------------------------------------
// Launch
// ---------------------------------------------------------------------------
extern "C" void kernel_launch(void* const* d_in, const int* in_sizes, int n_in,
                              void* d_out, int out_size) {
    const float* inp   = (const float*)d_in[0];   // [512,1024,128]
    const float* W_ih  = (const float*)d_in[1];   // [512,128]
    const float* W_hh  = (const float*)d_in[2];   // [512,128]
    const float* b_ih  = (const float*)d_in[3];   // [512]
    const float* b_hh  = (const float*)d_in[4];   // [512]
    const float* W_lin = (const float*)d_in[5];   // [128,128]
    const float* b_lin = (const float*)d_in[6];   // [128]
    float* out = (float*)d_out;                   // [129,1024,128]

    (void)in_sizes; (void)n_in; (void)out_size;

    cudaFuncSetAttribute(xgemm_kernel, cudaFuncAttributeMaxDynamicSharedMemorySize,
                         XGEMM_SMEM);
    cudaFuncSetAttribute(lstm_kernel, cudaFuncAttributeMaxDynamicSharedMemorySize,
                         LSTM_SMEM);

    setup_kernel<<<256, 256>>>(W_ih, W_hh, b_ih, b_hh, W_lin, b_lin);
    xgemm_kernel<<<dim3(4096, 4), 256, XGEMM_SMEM>>>(inp, W_ih, b_ih, b_hh);
    lstm_kernel<<<NBLK, 512, LSTM_SMEM>>>(W_lin, b_lin, out);
}

// round 2
// speedup vs baseline: 1.0520x; 1.0520x over previous
#include <cuda_runtime.h>
#include <cuda_fp16.h>
#include <cstdint>

// Problem dims (fixed by the dataset)
#define T_STEPS 512
#define BATCH   1024
#define DIM     128
#define HID     128
#define G4      512        // 4*HID
#define FUT     128
#define ROWS_PER_BLK 8
#define NBLK    (BATCH / ROWS_PER_BLK)   // 128

// ---------------------------------------------------------------------------
// Device scratch (allocation-free rule: static __device__ globals)
// ---------------------------------------------------------------------------
__device__ __half g_gxh[(size_t)T_STEPS * BATCH * G4];  // 512 MB fp16 x-gates (+bias)
__device__ __half g_whh_h[G4 * HID];                    // fp16 W_hh
__device__ __half g_weff_h[G4 * HID];                   // fp16 W_eff = W_hh + W_ih@W_lin
__device__ float  g_beff[G4];                           // b_eff = b_ih+b_hh + W_ih@b_lin

// ---------------------------------------------------------------------------
// packed f32x2 helpers (sm_103a)
// ---------------------------------------------------------------------------
__device__ __forceinline__ unsigned long long pack2(float x, float y) {
    unsigned long long r;
    asm("mov.b64 %0, {%1, %2};" : "=l"(r) : "f"(x), "f"(y));
    return r;
}
__device__ __forceinline__ void unpack2(unsigned long long v, float& x, float& y) {
    asm("mov.b64 {%0, %1}, %2;" : "=f"(x), "=f"(y) : "l"(v));
}
__device__ __forceinline__ void fma2(unsigned long long& d, unsigned long long a,
                                     unsigned long long b) {
    asm("fma.rn.f32x2 %0, %1, %2, %0;" : "+l"(d) : "l"(a), "l"(b));
}

__device__ __forceinline__ float sigf(float x) {
    return 1.0f / (1.0f + __expf(-x));
}
__device__ __forceinline__ float tanhfast(float x) {
    float ax = fabsf(x);
    float e  = __expf(-2.0f * ax);
    float r  = (1.0f - e) / (1.0f + e);
    return copysignf(r, x);
}

// ---------------------------------------------------------------------------
// Setup: W_eff, b_eff, fp16 copies.  65536 threads.
// ---------------------------------------------------------------------------
__global__ void setup_kernel(const float* __restrict__ W_ih,
                             const float* __restrict__ W_hh,
                             const float* __restrict__ b_ih,
                             const float* __restrict__ b_hh,
                             const float* __restrict__ W_lin,
                             const float* __restrict__ b_lin) {
    int idx = blockIdx.x * blockDim.x + threadIdx.x;   // 0 .. 65535
    int g = idx >> 7;
    int k = idx & 127;
    // W_eff[g][k] = W_hh[g][k] + sum_j W_ih[g][j] * W_lin[j][k]
    float s = W_hh[g * HID + k];
    #pragma unroll 8
    for (int j = 0; j < DIM; j++)
        s = fmaf(W_ih[g * DIM + j], W_lin[j * HID + k], s);
    g_weff_h[idx] = __float2half(s);
    g_whh_h[idx]  = __float2half(W_hh[idx]);
    if (idx < G4) {
        float b = b_ih[idx] + b_hh[idx];
        #pragma unroll 8
        for (int j = 0; j < DIM; j++)
            b = fmaf(W_ih[idx * DIM + j], b_lin[j], b);
        g_beff[idx] = b;
    }
}

// ---------------------------------------------------------------------------
// xgemm: G_x = inp @ W_ih^T + (b_ih + b_hh), stored fp16 to g_gxh.
//   A [M=524288, K=128] row-major, W [512, 128] row-major, C [M, 512]
//   128x128 tile / CTA, 256 threads, 8x8 micro-tile, packed fma.rn.f32x2
// ---------------------------------------------------------------------------
#define XGEMM_SMEM ((128 * 64 + 64 * 130) * 4)

__global__ void __launch_bounds__(256)
xgemm_kernel(const float* __restrict__ A, const float* __restrict__ W,
             const float* __restrict__ b_ih, const float* __restrict__ b_hh) {
    extern __shared__ float sm[];
    float* Asub = sm;                 // [128][64]
    float* Bsub = sm + 128 * 64;      // [64][130]  (transposed: [k][n])

    const int tid = threadIdx.x;
    const int tx  = tid & 15;          // n dimension
    const int ty  = tid >> 4;          // m dimension
    const size_t m0 = (size_t)blockIdx.x * 128;
    const int    n0 = blockIdx.y * 128;

    unsigned long long acc[8][4];
    #pragma unroll
    for (int i = 0; i < 8; i++)
        #pragma unroll
        for (int j = 0; j < 4; j++) acc[i][j] = 0ULL;

    for (int kc = 0; kc < 2; kc++) {
        const int k0 = kc * 64;
        // load A chunk [128 m][64 k], coalesced float4
        #pragma unroll
        for (int j = 0; j < 8; j++) {
            int idx = tid + j * 256;
            int m   = idx >> 4;
            int kf  = idx & 15;
            float4 v = *(const float4*)(A + (m0 + m) * 128 + k0 + kf * 4);
            *(float4*)(Asub + m * 64 + kf * 4) = v;
        }
        // load B chunk transposed into [k][n]
        #pragma unroll
        for (int j = 0; j < 8; j++) {
            int idx = tid + j * 256;
            int n   = idx >> 4;
            int kf  = idx & 15;
            float4 v = *(const float4*)(W + (size_t)(n0 + n) * 128 + k0 + kf * 4);
            Bsub[(kf * 4 + 0) * 130 + n] = v.x;
            Bsub[(kf * 4 + 1) * 130 + n] = v.y;
            Bsub[(kf * 4 + 2) * 130 + n] = v.z;
            Bsub[(kf * 4 + 3) * 130 + n] = v.w;
        }
        __syncthreads();

        #pragma unroll 4
        for (int k = 0; k < 64; k++) {
            unsigned long long a2[8];
            #pragma unroll
            for (int i = 0; i < 8; i++) {
                float a = Asub[(ty * 8 + i) * 64 + k];
                a2[i] = pack2(a, a);
            }
            unsigned long long b2[4];
            #pragma unroll
            for (int j = 0; j < 4; j++)
                b2[j] = *(const unsigned long long*)(Bsub + k * 130 + tx * 2 + j * 32);
            #pragma unroll
            for (int i = 0; i < 8; i++)
                #pragma unroll
                for (int j = 0; j < 4; j++)
                    fma2(acc[i][j], a2[i], b2[j]);
        }
        __syncthreads();
    }

    // epilogue: + bias, convert to fp16, store to g_gxh
    float2 bias[4];
    #pragma unroll
    for (int j = 0; j < 4; j++) {
        int n = n0 + tx * 2 + j * 32;
        bias[j].x = b_ih[n] + b_hh[n];
        bias[j].y = b_ih[n + 1] + b_hh[n + 1];
    }
    #pragma unroll
    for (int i = 0; i < 8; i++) {
        size_t m = m0 + ty * 8 + i;
        #pragma unroll
        for (int j = 0; j < 4; j++) {
            float x, y;
            unpack2(acc[i][j], x, y);
            __half2 hv = __floats2half2_rn(x + bias[j].x, y + bias[j].y);
            *(__half2*)(g_gxh + m * G4 + n0 + tx * 2 + j * 32) = hv;
        }
    }
}

// ---------------------------------------------------------------------------
// Persistent LSTM recurrence.  128 CTAs x 512 threads; 8 batch rows / CTA.
//
// Dot phase: thread (u = tid&127, q = tid>>7) computes gate g = q*128+u for
//   ALL 8 rows -> w-load/cvt/splat amortized 8x; rows packed pairwise into
//   f32x2 accumulators; h row-pairs read directly as ulonglong2 from smem.
// Update phase: thread (u, rg=q) combines the 4 gates of unit u for rows
//   {2rg, 2rg+1} via a smem gate buffer; c lives in registers.
//
// smem: wg   [512][65] half2 (fp16 W_hh, later W_eff)   133120 B
//       wlf  [128][130] float (fp32 W_lin)               66560 B
//       hbuf [128 k][8 r] float                           4096 B
//       gbuf [4 q][8 r][128 u] float                     16384 B
// ---------------------------------------------------------------------------
#define WG_BYTES   (512 * 65 * 4)
#define WLF_BYTES  (128 * 130 * 4)
#define HBUF_BYTES (128 * 8 * 4)
#define GBUF_BYTES (4 * 8 * 128 * 4)
#define LSTM_SMEM  (WG_BYTES + WLF_BYTES + HBUF_BYTES + GBUF_BYTES)

// 8-row gate dot-product over k=0..127 with fp16 weights, f32x2 math.
__device__ __forceinline__ void dot8(const __half2* __restrict__ wrow,
                                     const float* __restrict__ hbuf,
                                     unsigned long long acc[4]) {
    #pragma unroll 16
    for (int kk = 0; kk < 64; kk++) {
        float2 wf = __half22float2(wrow[kk]);
        unsigned long long wA = pack2(wf.x, wf.x);
        unsigned long long wB = pack2(wf.y, wf.y);
        ulonglong2 hA  = *(const ulonglong2*)(hbuf + 16 * kk);       // k=2kk, rows 0..3
        ulonglong2 hA2 = *(const ulonglong2*)(hbuf + 16 * kk + 4);   // k=2kk, rows 4..7
        ulonglong2 hB  = *(const ulonglong2*)(hbuf + 16 * kk + 8);   // k=2kk+1, rows 0..3
        ulonglong2 hB2 = *(const ulonglong2*)(hbuf + 16 * kk + 12);  // k=2kk+1, rows 4..7
        fma2(acc[0], wA, hA.x);  fma2(acc[1], wA, hA.y);
        fma2(acc[2], wA, hA2.x); fma2(acc[3], wA, hA2.y);
        fma2(acc[0], wB, hB.x);  fma2(acc[1], wB, hB.y);
        fma2(acc[2], wB, hB2.x); fma2(acc[3], wB, hB2.y);
    }
}

// scatter 8 gate values (row-pairs in acc) to gbuf[q][r][u]
__device__ __forceinline__ void scatter_gates(float* __restrict__ gbuf,
                                              const unsigned long long acc[4],
                                              int u, int q) {
    #pragma unroll
    for (int p = 0; p < 4; p++) {
        float g0, g1;
        unpack2(acc[p], g0, g1);
        gbuf[q * 1024 + (2 * p) * 128 + u]     = g0;
        gbuf[q * 1024 + (2 * p + 1) * 128 + u] = g1;
    }
}

// gate order i,f,g,o; thread handles unit u, rows r0, r0+1
__device__ __forceinline__ void cell_update(const float* __restrict__ gbuf,
                                            float* __restrict__ hbuf,
                                            int u, int r0, float& c0, float& c1) {
    float i0 = sigf(gbuf[0 * 1024 + r0 * 128 + u]);
    float i1 = sigf(gbuf[0 * 1024 + (r0 + 1) * 128 + u]);
    float f0 = sigf(gbuf[1 * 1024 + r0 * 128 + u]);
    float f1 = sigf(gbuf[1 * 1024 + (r0 + 1) * 128 + u]);
    float g0 = tanhfast(gbuf[2 * 1024 + r0 * 128 + u]);
    float g1 = tanhfast(gbuf[2 * 1024 + (r0 + 1) * 128 + u]);
    float o0 = sigf(gbuf[3 * 1024 + r0 * 128 + u]);
    float o1 = sigf(gbuf[3 * 1024 + (r0 + 1) * 128 + u]);
    c0 = fmaf(f0, c0, i0 * g0);
    c1 = fmaf(f1, c1, i1 * g1);
    float2 hn;
    hn.x = o0 * tanhfast(c0);
    hn.y = o1 * tanhfast(c1);
    *(float2*)(hbuf + u * 8 + r0) = hn;   // r0 even -> 8B aligned
}

// out_t[r][u] = W_lin[u]·h[:,r] + b_lin[u]; k-range split by q, reduce via gbuf.
// Uses 2 __syncthreads().
__device__ __forceinline__ void emit_out(const float* __restrict__ wlf,
                                         const float* __restrict__ hbuf,
                                         float* __restrict__ gbuf,
                                         int u, int q, float blin, int b0,
                                         float* __restrict__ out_t) {
    unsigned long long acc[4] = {0ULL, 0ULL, 0ULL, 0ULL};
    const float* wlrow = wlf + u * 130 + q * 32;
    const float* hb    = hbuf + q * 32 * 8;
    #pragma unroll
    for (int kk = 0; kk < 16; kk++) {
        float2 wf = *(const float2*)(wlrow + 2 * kk);
        unsigned long long wA = pack2(wf.x, wf.x);
        unsigned long long wB = pack2(wf.y, wf.y);
        ulonglong2 hA  = *(const ulonglong2*)(hb + 16 * kk);
        ulonglong2 hA2 = *(const ulonglong2*)(hb + 16 * kk + 4);
        ulonglong2 hB  = *(const ulonglong2*)(hb + 16 * kk + 8);
        ulonglong2 hB2 = *(const ulonglong2*)(hb + 16 * kk + 12);
        fma2(acc[0], wA, hA.x);  fma2(acc[1], wA, hA.y);
        fma2(acc[2], wA, hA2.x); fma2(acc[3], wA, hA2.y);
        fma2(acc[0], wB, hB.x);  fma2(acc[1], wB, hB.y);
        fma2(acc[2], wB, hB2.x); fma2(acc[3], wB, hB2.y);
    }
    scatter_gates(gbuf, acc, u, q);
    __syncthreads();
    // reduce partials: thread (u, rg=q) handles rows 2q, 2q+1
    int r0 = 2 * q;
    float o0 = blin, o1 = blin;
    #pragma unroll
    for (int qq = 0; qq < 4; qq++) {
        o0 += gbuf[qq * 1024 + r0 * 128 + u];
        o1 += gbuf[qq * 1024 + (r0 + 1) * 128 + u];
    }
    out_t[(size_t)(b0 + r0) * HID + u]     = o0;
    out_t[(size_t)(b0 + r0 + 1) * HID + u] = o1;
    __syncthreads();   // gbuf free for reuse
}

__global__ void __launch_bounds__(512, 1)
lstm_kernel(const float* __restrict__ W_lin, const float* __restrict__ b_lin,
            float* __restrict__ out) {
    extern __shared__ char smem[];
    __half2* wg   = (__half2*)smem;                               // [512][65]
    float*   wlf  = (float*)(smem + WG_BYTES);                    // [128][130]
    float*   hbuf = (float*)(smem + WG_BYTES + WLF_BYTES);        // [128][8]
    float*   gbuf = (float*)(smem + WG_BYTES + WLF_BYTES + HBUF_BYTES); // [4][8][128]

    const int tid = threadIdx.x;
    const int u   = tid & 127;     // unit
    const int q   = tid >> 7;      // gate (dot phase) / row-group (update phase)
    const int gg  = q * 128 + u;   // gate row in W
    const int r0  = 2 * q;         // update-phase local row pair
    const int b0  = blockIdx.x * ROWS_PER_BLK;

    // load fp16 W_hh into smem (coalesced, padded rows)
    const __half2* whh2 = (const __half2*)g_whh_h;
    for (int i = tid; i < G4 * 64; i += 512) {
        int g = i >> 6, kk = i & 63;
        wg[g * 65 + kk] = whh2[i];
    }
    // fp32 W_lin
    for (int i = tid; i < HID * HID; i += 512) {
        int uu = i >> 7, k = i & 127;
        wlf[uu * 130 + k] = W_lin[i];
    }
    for (int i = tid; i < 128 * 8; i += 512) hbuf[i] = 0.0f;
    float c0 = 0.0f, c1 = 0.0f;
    const float blin = b_lin[u];
    __syncthreads();

    const __half2* wrow = wg + gg * 65;

    // prefetch G_x for t = 0 (8 rows of gate gg)
    __half gx8[8];
    {
        const __half* gxp = g_gxh + (size_t)b0 * G4 + gg;
        #pragma unroll
        for (int r = 0; r < 8; r++) gx8[r] = gxp[(size_t)r * G4];
    }

    // ---------------- main scan over T ----------------
    for (int t = 0; t < T_STEPS; t++) {
        unsigned long long acc[4];
        #pragma unroll
        for (int p = 0; p < 4; p++)
            acc[p] = pack2(__half2float(gx8[2 * p]), __half2float(gx8[2 * p + 1]));

        // prefetch next step's G_x (hidden under the k-loop)
        if (t + 1 < T_STEPS) {
            const __half* gxp = g_gxh + ((size_t)(t + 1) * BATCH + b0) * G4 + gg;
            #pragma unroll
            for (int r = 0; r < 8; r++) gx8[r] = gxp[(size_t)r * G4];
        }

        dot8(wrow, hbuf, acc);
        scatter_gates(gbuf, acc, u, q);
        __syncthreads();
        cell_update(gbuf, hbuf, u, r0, c0, c1);
        __syncthreads();
    }

    // ---------------- out[0] ----------------
    emit_out(wlf, hbuf, gbuf, u, q, blin, b0, out);

    // swap in W_eff (gates = W_eff h + b_eff)
    const __half2* weff2 = (const __half2*)g_weff_h;
    for (int i = tid; i < G4 * 64; i += 512) {
        int g = i >> 6, kk = i & 63;
        wg[g * 65 + kk] = weff2[i];
    }
    const float beff = g_beff[gg];
    __syncthreads();

    // ---------------- future steps ----------------
    for (int ft = 0; ft < FUT; ft++) {
        unsigned long long acc[4];
        unsigned long long b2 = pack2(beff, beff);
        #pragma unroll
        for (int p = 0; p < 4; p++) acc[p] = b2;

        dot8(wrow, hbuf, acc);
        scatter_gates(gbuf, acc, u, q);
        __syncthreads();
        cell_update(gbuf, hbuf, u, r0, c0, c1);
        __syncthreads();

        emit_out(wlf, hbuf, gbuf, u, q, blin, b0,
                 out + (size_t)(1 + ft) * BATCH * HID);
    }
}

// ---------------------------------------------------------------------------
// Launch
// ---------------------------------------------------------------------------
extern "C" void kernel_launch(void* const* d_in, const int* in_sizes, int n_in,
                              void* d_out, int out_size) {
    const float* inp   = (const float*)d_in[0];   // [512,1024,128]
    const float* W_ih  = (const float*)d_in[1];   // [512,128]
    const float* W_hh  = (const float*)d_in[2];   // [512,128]
    const float* b_ih  = (const float*)d_in[3];   // [512]
    const float* b_hh  = (const float*)d_in[4];   // [512]
    const float* W_lin = (const float*)d_in[5];   // [128,128]
    const float* b_lin = (const float*)d_in[6];   // [128]
    float* out = (float*)d_out;                   // [129,1024,128]

    (void)in_sizes; (void)n_in; (void)out_size;

    cudaFuncSetAttribute(xgemm_kernel, cudaFuncAttributeMaxDynamicSharedMemorySize,
                         XGEMM_SMEM);
    cudaFuncSetAttribute(lstm_kernel, cudaFuncAttributeMaxDynamicSharedMemorySize,
                         LSTM_SMEM);

    setup_kernel<<<256, 256>>>(W_ih, W_hh, b_ih, b_hh, W_lin, b_lin);
    xgemm_kernel<<<dim3(4096, 4), 256, XGEMM_SMEM>>>(inp, W_ih, b_ih, b_hh);
    lstm_kernel<<<NBLK, 512, LSTM_SMEM>>>(W_lin, b_lin, out);
}

// round 4
// speedup vs baseline: 1.0870x; 1.0333x over previous
#include <cuda_runtime.h>
#include <cuda_fp16.h>
#include <cstdint>

// Problem dims (fixed by the dataset)
#define T_STEPS 512
#define BATCH   1024
#define DIM     128
#define HID     128
#define G4      512        // 4*HID
#define FUT     128
#define ROWS_PER_BLK 8
#define NBLK    (BATCH / ROWS_PER_BLK)   // 128

// ---------------------------------------------------------------------------
// Device scratch (allocation-free rule: static __device__ globals)
// ---------------------------------------------------------------------------
__device__ __half g_gxh[(size_t)T_STEPS * BATCH * G4];  // 512 MB fp16 x-gates (+bias)
__device__ __half g_whh_h[G4 * HID];                    // fp16 W_hh
__device__ __half g_weff_h[G4 * HID];                   // fp16 W_eff = W_hh + W_ih@W_lin
__device__ float  g_beff[G4];                           // b_eff = b_ih+b_hh + W_ih@b_lin

// ---------------------------------------------------------------------------
// packed f32x2 + fast-math helpers (sm_103a)
// ---------------------------------------------------------------------------
__device__ __forceinline__ unsigned long long pack2(float x, float y) {
    unsigned long long r;
    asm("mov.b64 %0, {%1, %2};" : "=l"(r) : "f"(x), "f"(y));
    return r;
}
__device__ __forceinline__ void unpack2(unsigned long long v, float& x, float& y) {
    asm("mov.b64 {%0, %1}, %2;" : "=f"(x), "=f"(y) : "l"(v));
}
__device__ __forceinline__ void fma2(unsigned long long& d, unsigned long long a,
                                     unsigned long long b) {
    asm("fma.rn.f32x2 %0, %1, %2, %0;" : "+l"(d) : "l"(a), "l"(b));
}
__device__ __forceinline__ float ex2f(float x) {
    float r; asm("ex2.approx.f32 %0, %1;" : "=f"(r) : "f"(x)); return r;
}
__device__ __forceinline__ float rcpf(float x) {
    float r; asm("rcp.approx.f32 %0, %1;" : "=f"(r) : "f"(x)); return r;
}
// sigmoid(x) = 1/(1+exp(-x)) = rcp(1 + 2^(-x*log2e))
__device__ __forceinline__ float sigf(float x) {
    return rcpf(1.0f + ex2f(-1.4426950409f * x));
}
// tanh(x) = 1 - 2/(exp(2x)+1) = 1 - 2*rcp(1 + 2^(x*2*log2e))
__device__ __forceinline__ float tanhfast(float x) {
    return fmaf(-2.0f, rcpf(1.0f + ex2f(2.8853900818f * x)), 1.0f);
}

// ---------------------------------------------------------------------------
// Dummy kernel: shifts launch indices so ncu (-s 5 -c 1) profiles lstm_kernel
// ---------------------------------------------------------------------------
__global__ void dummy_kernel() {}

// ---------------------------------------------------------------------------
// Setup: W_eff, b_eff, fp16 copies.  65536 threads.
// ---------------------------------------------------------------------------
__global__ void setup_kernel(const float* __restrict__ W_ih,
                             const float* __restrict__ W_hh,
                             const float* __restrict__ b_ih,
                             const float* __restrict__ b_hh,
                             const float* __restrict__ W_lin,
                             const float* __restrict__ b_lin) {
    int idx = blockIdx.x * blockDim.x + threadIdx.x;   // 0 .. 65535
    int g = idx >> 7;
    int k = idx & 127;
    // W_eff[g][k] = W_hh[g][k] + sum_j W_ih[g][j] * W_lin[j][k]
    float s = W_hh[g * HID + k];
    #pragma unroll 8
    for (int j = 0; j < DIM; j++)
        s = fmaf(W_ih[g * DIM + j], W_lin[j * HID + k], s);
    g_weff_h[idx] = __float2half(s);
    g_whh_h[idx]  = __float2half(W_hh[idx]);
    if (idx < G4) {
        float b = b_ih[idx] + b_hh[idx];
        #pragma unroll 8
        for (int j = 0; j < DIM; j++)
            b = fmaf(W_ih[idx * DIM + j], b_lin[j], b);
        g_beff[idx] = b;
    }
}

// ---------------------------------------------------------------------------
// xgemm: G_x = inp @ W_ih^T + (b_ih + b_hh), stored fp16 to g_gxh.
//   A [M=524288, K=128] row-major, W [512, 128] row-major, C [M, 512]
//   128x128 tile / CTA, 256 threads, 8x8 micro-tile, packed fma.rn.f32x2
// ---------------------------------------------------------------------------
#define XGEMM_SMEM ((128 * 64 + 64 * 130) * 4)

__global__ void __launch_bounds__(256)
xgemm_kernel(const float* __restrict__ A, const float* __restrict__ W,
             const float* __restrict__ b_ih, const float* __restrict__ b_hh) {
    extern __shared__ float sm[];
    float* Asub = sm;                 // [128][64]
    float* Bsub = sm + 128 * 64;      // [64][130]  (transposed: [k][n])

    const int tid = threadIdx.x;
    const int tx  = tid & 15;          // n dimension
    const int ty  = tid >> 4;          // m dimension
    const size_t m0 = (size_t)blockIdx.x * 128;
    const int    n0 = blockIdx.y * 128;

    unsigned long long acc[8][4];
    #pragma unroll
    for (int i = 0; i < 8; i++)
        #pragma unroll
        for (int j = 0; j < 4; j++) acc[i][j] = 0ULL;

    for (int kc = 0; kc < 2; kc++) {
        const int k0 = kc * 64;
        #pragma unroll
        for (int j = 0; j < 8; j++) {
            int idx = tid + j * 256;
            int m   = idx >> 4;
            int kf  = idx & 15;
            float4 v = *(const float4*)(A + (m0 + m) * 128 + k0 + kf * 4);
            *(float4*)(Asub + m * 64 + kf * 4) = v;
        }
        #pragma unroll
        for (int j = 0; j < 8; j++) {
            int idx = tid + j * 256;
            int n   = idx >> 4;
            int kf  = idx & 15;
            float4 v = *(const float4*)(W + (size_t)(n0 + n) * 128 + k0 + kf * 4);
            Bsub[(kf * 4 + 0) * 130 + n] = v.x;
            Bsub[(kf * 4 + 1) * 130 + n] = v.y;
            Bsub[(kf * 4 + 2) * 130 + n] = v.z;
            Bsub[(kf * 4 + 3) * 130 + n] = v.w;
        }
        __syncthreads();

        #pragma unroll 4
        for (int k = 0; k < 64; k++) {
            unsigned long long a2[8];
            #pragma unroll
            for (int i = 0; i < 8; i++) {
                float a = Asub[(ty * 8 + i) * 64 + k];
                a2[i] = pack2(a, a);
            }
            unsigned long long b2[4];
            #pragma unroll
            for (int j = 0; j < 4; j++)
                b2[j] = *(const unsigned long long*)(Bsub + k * 130 + tx * 2 + j * 32);
            #pragma unroll
            for (int i = 0; i < 8; i++)
                #pragma unroll
                for (int j = 0; j < 4; j++)
                    fma2(acc[i][j], a2[i], b2[j]);
        }
        __syncthreads();
    }

    float2 bias[4];
    #pragma unroll
    for (int j = 0; j < 4; j++) {
        int n = n0 + tx * 2 + j * 32;
        bias[j].x = b_ih[n] + b_hh[n];
        bias[j].y = b_ih[n + 1] + b_hh[n + 1];
    }
    #pragma unroll
    for (int i = 0; i < 8; i++) {
        size_t m = m0 + ty * 8 + i;
        #pragma unroll
        for (int j = 0; j < 4; j++) {
            float x, y;
            unpack2(acc[i][j], x, y);
            __half2 hv = __floats2half2_rn(x + bias[j].x, y + bias[j].y);
            *(__half2*)(g_gxh + m * G4 + n0 + tx * 2 + j * 32) = hv;
        }
    }
}

// ---------------------------------------------------------------------------
// Persistent LSTM recurrence.  128 CTAs x 1024 threads; 8 batch rows / CTA.
//
// Dot phase: thread (u = tid&127, q = (tid>>7)&3, kh = tid>>9) computes the
//   k-half [kh*64, kh*64+64) of gate g = q*128+u for ALL 8 rows; partials go
//   to pbuf[kh][q][r][u].  8 warps/SMSP for latency hiding; fma.rn.f32x2.
// Update phase: thread (u, rr = tid>>7) owns unit u, row rr: sums the 2
//   k-half partials of each gate, applies activations (ex2/rcp approx, no
//   div.rn), keeps c in a register, writes h to hbuf.
//
// smem: wg   [512][65] half2 (fp16 W_hh, later W_eff)   133120 B
//       wl2  [128][65] half2 (fp16 W_lin)                33280 B
//       hbuf [128 k][8 r] float                           4096 B
//       pbuf [2 kh][4 q][8 r][128 u] float               32768 B
//       total                                           203264 B
// ---------------------------------------------------------------------------
#define WG_BYTES   (512 * 65 * 4)
#define WL_BYTES   (128 * 65 * 4)
#define HBUF_BYTES (128 * 8 * 4)
#define PBUF_BYTES (2 * 4 * 8 * 128 * 4)
#define LSTM_SMEM  (WG_BYTES + WL_BYTES + HBUF_BYTES + PBUF_BYTES)

// 8-row x 64-k gate partial dot product: fp16 weights, f32x2 math.
__device__ __forceinline__ void dot_half(const __half2* __restrict__ wrow,
                                         const float* __restrict__ hb,
                                         unsigned long long acc[4]) {
    #pragma unroll 4
    for (int kk = 0; kk < 32; kk++) {
        float2 wf = __half22float2(wrow[kk]);
        unsigned long long wA = pack2(wf.x, wf.x);
        unsigned long long wB = pack2(wf.y, wf.y);
        ulonglong2 hA  = *(const ulonglong2*)(hb + 16 * kk);       // k even, rows 0..3
        ulonglong2 hA2 = *(const ulonglong2*)(hb + 16 * kk + 4);   // k even, rows 4..7
        ulonglong2 hB  = *(const ulonglong2*)(hb + 16 * kk + 8);   // k odd,  rows 0..3
        ulonglong2 hB2 = *(const ulonglong2*)(hb + 16 * kk + 12);  // k odd,  rows 4..7
        fma2(acc[0], wA, hA.x);  fma2(acc[1], wA, hA.y);
        fma2(acc[2], wA, hA2.x); fma2(acc[3], wA, hA2.y);
        fma2(acc[0], wB, hB.x);  fma2(acc[1], wB, hB.y);
        fma2(acc[2], wB, hB2.x); fma2(acc[3], wB, hB2.y);
    }
}

// scatter 8 row-values (row pairs packed in acc) to pbuf[slot][r][u]
__device__ __forceinline__ void scatter_p(float* __restrict__ pslot,
                                          const unsigned long long acc[4], int u) {
    #pragma unroll
    for (int p = 0; p < 4; p++) {
        float g0, g1;
        unpack2(acc[p], g0, g1);
        pslot[(2 * p) * 128 + u]     = g0;
        pslot[(2 * p + 1) * 128 + u] = g1;
    }
}

__global__ void __launch_bounds__(1024, 1)
lstm_kernel(const float* __restrict__ W_lin, const float* __restrict__ b_lin,
            float* __restrict__ out) {
    extern __shared__ char smem[];
    __half2* wg   = (__half2*)smem;                                   // [512][65]
    __half2* wl2  = (__half2*)(smem + WG_BYTES);                      // [128][65]
    float*   hbuf = (float*)(smem + WG_BYTES + WL_BYTES);             // [128][8]
    float*   pbuf = (float*)(smem + WG_BYTES + WL_BYTES + HBUF_BYTES);// [2][4][8][128]

    const int tid = threadIdx.x;
    const int u   = tid & 127;          // unit
    const int q   = (tid >> 7) & 3;     // gate (dot phase)
    const int kh  = tid >> 9;           // k-half (dot phase)
    const int gg  = q * 128 + u;        // gate row in W
    const int rr  = tid >> 7;           // row (update phase, 0..7)
    const int b0  = blockIdx.x * ROWS_PER_BLK;

    // fp16 W_hh -> smem (coalesced, padded rows, conflict-free stride 65)
    const __half2* whh2 = (const __half2*)g_whh_h;
    for (int i = tid; i < G4 * 64; i += 1024) {
        int g = i >> 6, kk = i & 63;
        wg[g * 65 + kk] = whh2[i];
    }
    // fp32 W_lin -> fp16 smem
    for (int i = tid; i < HID * 64; i += 1024) {
        int uu = i >> 6, kk = i & 63;
        float2 wv = *(const float2*)(W_lin + uu * HID + 2 * kk);
        wl2[uu * 65 + kk] = __floats2half2_rn(wv.x, wv.y);
    }
    hbuf[tid & 1023] = 0.0f;
    float c = 0.0f;                       // cell state for (u, rr)
    const float blin = b_lin[u];
    __syncthreads();

    const __half2* wrow = wg + gg * 65 + kh * 32;
    const float*   hb   = hbuf + kh * 512;
    float* pslot = pbuf + kh * 4096 + q * 1024;

    // prefetch G_x for t = 0 (kh==0 threads carry the bias/x term)
    __half gx8[8];
    #pragma unroll
    for (int r = 0; r < 8; r++) gx8[r] = __float2half(0.0f);
    if (kh == 0) {
        const __half* gxp = g_gxh + (size_t)b0 * G4 + gg;
        #pragma unroll
        for (int r = 0; r < 8; r++) gx8[r] = gxp[(size_t)r * G4];
    }

    // ---------------- main scan over T ----------------
    for (int t = 0; t < T_STEPS; t++) {
        unsigned long long acc[4];
        #pragma unroll
        for (int p = 0; p < 4; p++)
            acc[p] = pack2(__half2float(gx8[2 * p]), __half2float(gx8[2 * p + 1]));

        if (kh == 0 && t + 1 < T_STEPS) {
            const __half* gxp = g_gxh + ((size_t)(t + 1) * BATCH + b0) * G4 + gg;
            #pragma unroll
            for (int r = 0; r < 8; r++) gx8[r] = gxp[(size_t)r * G4];
        }

        dot_half(wrow, hb, acc);
        scatter_p(pslot, acc, u);
        __syncthreads();

        // update: thread (u, rr) handles one (unit, row)
        float ai = pbuf[0 * 1024 + rr * 128 + u] + pbuf[4096 + 0 * 1024 + rr * 128 + u];
        float af = pbuf[1 * 1024 + rr * 128 + u] + pbuf[4096 + 1 * 1024 + rr * 128 + u];
        float ag = pbuf[2 * 1024 + rr * 128 + u] + pbuf[4096 + 2 * 1024 + rr * 128 + u];
        float ao = pbuf[3 * 1024 + rr * 128 + u] + pbuf[4096 + 3 * 1024 + rr * 128 + u];
        c = fmaf(sigf(af), c, sigf(ai) * tanhfast(ag));
        hbuf[u * 8 + rr] = sigf(ao) * tanhfast(c);
        __syncthreads();
    }

    // ---------------- out[0] = W_lin h_T + b_lin ----------------
    {
        const int seg = kh * 4 + q;      // 8 k-segments of 16
        unsigned long long acc[4] = {0ULL, 0ULL, 0ULL, 0ULL};
        dot_segment:
        {
            const __half2* wl = wl2 + u * 65 + seg * 8;
            const float*   hs = hbuf + seg * 128;
            #pragma unroll
            for (int kk = 0; kk < 8; kk++) {
                float2 wf = __half22float2(wl[kk]);
                unsigned long long wA = pack2(wf.x, wf.x);
                unsigned long long wB = pack2(wf.y, wf.y);
                ulonglong2 hA  = *(const ulonglong2*)(hs + 16 * kk);
                ulonglong2 hA2 = *(const ulonglong2*)(hs + 16 * kk + 4);
                ulonglong2 hB  = *(const ulonglong2*)(hs + 16 * kk + 8);
                ulonglong2 hB2 = *(const ulonglong2*)(hs + 16 * kk + 12);
                fma2(acc[0], wA, hA.x);  fma2(acc[1], wA, hA.y);
                fma2(acc[2], wA, hA2.x); fma2(acc[3], wA, hA2.y);
                fma2(acc[0], wB, hB.x);  fma2(acc[1], wB, hB.y);
                fma2(acc[2], wB, hB2.x); fma2(acc[3], wB, hB2.y);
            }
        }
        scatter_p(pbuf + seg * 1024, acc, u);
        __syncthreads();
        float o = blin;
        #pragma unroll
        for (int s = 0; s < 8; s++) o += pbuf[s * 1024 + rr * 128 + u];
        out[(size_t)(b0 + rr) * HID + u] = o;
        __syncthreads();
    }

    // swap in W_eff (gates = W_eff h + b_eff)
    const __half2* weff2 = (const __half2*)g_weff_h;
    for (int i = tid; i < G4 * 64; i += 1024) {
        int g = i >> 6, kk = i & 63;
        wg[g * 65 + kk] = weff2[i];
    }
    const float beff = (kh == 0) ? g_beff[gg] : 0.0f;
    __syncthreads();

    // ---------------- future steps ----------------
    for (int ft = 0; ft < FUT; ft++) {
        unsigned long long acc[4];
        unsigned long long b2 = pack2(beff, beff);
        #pragma unroll
        for (int p = 0; p < 4; p++) acc[p] = b2;

        dot_half(wrow, hb, acc);
        scatter_p(pslot, acc, u);
        __syncthreads();

        float ai = pbuf[0 * 1024 + rr * 128 + u] + pbuf[4096 + 0 * 1024 + rr * 128 + u];
        float af = pbuf[1 * 1024 + rr * 128 + u] + pbuf[4096 + 1 * 1024 + rr * 128 + u];
        float ag = pbuf[2 * 1024 + rr * 128 + u] + pbuf[4096 + 2 * 1024 + rr * 128 + u];
        float ao = pbuf[3 * 1024 + rr * 128 + u] + pbuf[4096 + 3 * 1024 + rr * 128 + u];
        c = fmaf(sigf(af), c, sigf(ai) * tanhfast(ag));
        hbuf[u * 8 + rr] = sigf(ao) * tanhfast(c);
        __syncthreads();

        // emit out[1 + ft]
        const int seg = kh * 4 + q;
        unsigned long long pacc[4] = {0ULL, 0ULL, 0ULL, 0ULL};
        {
            const __half2* wl = wl2 + u * 65 + seg * 8;
            const float*   hs = hbuf + seg * 128;
            #pragma unroll
            for (int kk = 0; kk < 8; kk++) {
                float2 wf = __half22float2(wl[kk]);
                unsigned long long wA = pack2(wf.x, wf.x);
                unsigned long long wB = pack2(wf.y, wf.y);
                ulonglong2 hA  = *(const ulonglong2*)(hs + 16 * kk);
                ulonglong2 hA2 = *(const ulonglong2*)(hs + 16 * kk + 4);
                ulonglong2 hB  = *(const ulonglong2*)(hs + 16 * kk + 8);
                ulonglong2 hB2 = *(const ulonglong2*)(hs + 16 * kk + 12);
                fma2(pacc[0], wA, hA.x);  fma2(pacc[1], wA, hA.y);
                fma2(pacc[2], wA, hA2.x); fma2(pacc[3], wA, hA2.y);
                fma2(pacc[0], wB, hB.x);  fma2(pacc[1], wB, hB.y);
                fma2(pacc[2], wB, hB2.x); fma2(pacc[3], wB, hB2.y);
            }
        }
        scatter_p(pbuf + seg * 1024, pacc, u);
        __syncthreads();
        float o = blin;
        #pragma unroll
        for (int s = 0; s < 8; s++) o += pbuf[s * 1024 + rr * 128 + u];
        out[(size_t)(1 + ft) * BATCH * HID + (size_t)(b0 + rr) * HID + u] = o;
        __syncthreads();
    }
}

// ---------------------------------------------------------------------------
// Launch.  3 dummy launches first so ncu's "-s 5 -c 1" profiles lstm_kernel.
// ---------------------------------------------------------------------------
extern "C" void kernel_launch(void* const* d_in, const int* in_sizes, int n_in,
                              void* d_out, int out_size) {
    const float* inp   = (const float*)d_in[0];   // [512,1024,128]
    const float* W_ih  = (const float*)d_in[1];   // [512,128]
    const float* W_hh  = (const float*)d_in[2];   // [512,128]
    const float* b_ih  = (const float*)d_in[3];   // [512]
    const float* b_hh  = (const float*)d_in[4];   // [512]
    const float* W_lin = (const float*)d_in[5];   // [128,128]
    const float* b_lin = (const float*)d_in[6];   // [128]
    float* out = (float*)d_out;                   // [129,1024,128]

    (void)in_sizes; (void)n_in; (void)out_size;

    cudaFuncSetAttribute(xgemm_kernel, cudaFuncAttributeMaxDynamicSharedMemorySize,
                         XGEMM_SMEM);
    cudaFuncSetAttribute(lstm_kernel, cudaFuncAttributeMaxDynamicSharedMemorySize,
                         LSTM_SMEM);

    dummy_kernel<<<1, 32>>>();
    dummy_kernel<<<1, 32>>>();
    dummy_kernel<<<1, 32>>>();
    setup_kernel<<<256, 256>>>(W_ih, W_hh, b_ih, b_hh, W_lin, b_lin);
    xgemm_kernel<<<dim3(4096, 4), 256, XGEMM_SMEM>>>(inp, W_ih, b_ih, b_hh);
    lstm_kernel<<<NBLK, 1024, LSTM_SMEM>>>(W_lin, b_lin, out);
}

// round 8
// speedup vs baseline: 2.3841x; 2.1932x over previous
#include <cuda_runtime.h>
#include <cuda_fp16.h>
#include <cstdint>

// Problem dims (fixed by the dataset)
#define T_STEPS 512
#define BATCH   1024
#define DIM     128
#define HID     128
#define G4      512        // 4*HID
#define FUT     128

// recurrence config: 128 CTAs x 512 threads (16 warps), 8 batch rows / CTA
#define RPB   8                    // rows per block (MMA N)
#define NCTA  (BATCH / RPB)        // 128
#define TCN   512                  // threads

// ---------------------------------------------------------------------------
// Device scratch (allocation-free rule: static __device__ globals)
// ---------------------------------------------------------------------------
__device__ __half g_gxh[(size_t)T_STEPS * BATCH * G4];  // fp16 x-gates (+bias), [t][row][gate]
__device__ __half g_gxt[(size_t)T_STEPS * BATCH * G4];  // fragment-ordered: [t][cta][tid][8]
__device__ __half g_whh_h[G4 * HID];                    // fp16 W_hh (canonical)
__device__ __half g_weff_h[G4 * HID];                   // fp16 W_eff = W_hh + W_ih@W_lin
__device__ float  g_beff[G4];                           // b_eff = b_ih+b_hh + W_ih@b_lin

// ---------------------------------------------------------------------------
// helpers
// ---------------------------------------------------------------------------
__device__ __forceinline__ unsigned long long pack2(float x, float y) {
    unsigned long long r;
    asm("mov.b64 %0, {%1, %2};" : "=l"(r) : "f"(x), "f"(y));
    return r;
}
__device__ __forceinline__ void unpack2(unsigned long long v, float& x, float& y) {
    asm("mov.b64 {%0, %1}, %2;" : "=f"(x), "=f"(y) : "l"(v));
}
__device__ __forceinline__ void fma2(unsigned long long& d, unsigned long long a,
                                     unsigned long long b) {
    asm("fma.rn.f32x2 %0, %1, %2, %0;" : "+l"(d) : "l"(a), "l"(b));
}
__device__ __forceinline__ float tanha(float x) {
    float r; asm("tanh.approx.f32 %0, %1;" : "=f"(r) : "f"(x)); return r;
}
__device__ __forceinline__ float siga(float x) {      // sigmoid via tanh (1 MUFU)
    return fmaf(tanha(0.5f * x), 0.5f, 0.5f);
}
__device__ __forceinline__ uint32_t smem_u32(const void* p) {
    uint32_t a;
    asm("{ .reg .u64 t; cvta.to.shared.u64 t, %1; cvt.u32.u64 %0, t; }" : "=r"(a) : "l"(p));
    return a;
}
__device__ __forceinline__ float2 u2f2(uint32_t w) {
    __half2 h = *reinterpret_cast<__half2*>(&w);
    return __half22float2(h);
}

// mma.sync m16n8k16 f16*f16->f32 accumulate in place
__device__ __forceinline__ void mma16816(float* d, const uint32_t* a, const uint32_t* b) {
    asm volatile(
        "mma.sync.aligned.m16n8k16.row.col.f32.f16.f16.f32 "
        "{%0,%1,%2,%3}, {%4,%5,%6,%7}, {%8,%9}, {%0,%1,%2,%3};"
        : "+f"(d[0]), "+f"(d[1]), "+f"(d[2]), "+f"(d[3])
        : "r"(a[0]), "r"(a[1]), "r"(a[2]), "r"(a[3]), "r"(b[0]), "r"(b[1]));
}
__device__ __forceinline__ void ldsm_x4(uint32_t* r, uint32_t addr) {
    asm volatile("ldmatrix.sync.aligned.m8n8.x4.shared.b16 {%0,%1,%2,%3}, [%4];"
        : "=r"(r[0]), "=r"(r[1]), "=r"(r[2]), "=r"(r[3]) : "r"(addr));
}
__device__ __forceinline__ void ldsm_x2(uint32_t* r, uint32_t addr) {
    asm volatile("ldmatrix.sync.aligned.m8n8.x2.shared.b16 {%0,%1}, [%2];"
        : "=r"(r[0]), "=r"(r[1]) : "r"(addr));
}

// ---------------------------------------------------------------------------
// Setup: W_eff, b_eff, fp16 copies.  65536 threads.
// ---------------------------------------------------------------------------
__global__ void setup_kernel(const float* __restrict__ W_ih,
                             const float* __restrict__ W_hh,
                             const float* __restrict__ b_ih,
                             const float* __restrict__ b_hh,
                             const float* __restrict__ W_lin,
                             const float* __restrict__ b_lin) {
    int idx = blockIdx.x * blockDim.x + threadIdx.x;   // 0 .. 65535
    int g = idx >> 7;
    int k = idx & 127;
    float s = W_hh[g * HID + k];
    #pragma unroll 8
    for (int j = 0; j < DIM; j++)
        s = fmaf(W_ih[g * DIM + j], W_lin[j * HID + k], s);
    g_weff_h[idx] = __float2half(s);
    g_whh_h[idx]  = __float2half(W_hh[idx]);
    if (idx < G4) {
        float b = b_ih[idx] + b_hh[idx];
        #pragma unroll 8
        for (int j = 0; j < DIM; j++)
            b = fmaf(W_ih[idx * DIM + j], b_lin[j], b);
        g_beff[idx] = b;
    }
}

// ---------------------------------------------------------------------------
// xgemm: G_x = inp @ W_ih^T + (b_ih + b_hh), fp16 to g_gxh [t*B+row][gate]
// ---------------------------------------------------------------------------
#define XGEMM_SMEM ((128 * 64 + 64 * 130) * 4)

__global__ void __launch_bounds__(256)
xgemm_kernel(const float* __restrict__ A, const float* __restrict__ W,
             const float* __restrict__ b_ih, const float* __restrict__ b_hh) {
    extern __shared__ char smraw[];
    float* smf = (float*)smraw;
    float* Asub = smf;                 // [128][64]
    float* Bsub = smf + 128 * 64;      // [64][130]

    const int tid = threadIdx.x;
    const int tx  = tid & 15;
    const int ty  = tid >> 4;
    const size_t m0 = (size_t)blockIdx.x * 128;
    const int    n0 = blockIdx.y * 128;

    unsigned long long acc[8][4];
    #pragma unroll
    for (int i = 0; i < 8; i++)
        #pragma unroll
        for (int j = 0; j < 4; j++) acc[i][j] = 0ULL;

    for (int kc = 0; kc < 2; kc++) {
        const int k0 = kc * 64;
        #pragma unroll
        for (int j = 0; j < 8; j++) {
            int idx = tid + j * 256;
            int m   = idx >> 4;
            int kf  = idx & 15;
            float4 v = *(const float4*)(A + (m0 + m) * 128 + k0 + kf * 4);
            *(float4*)(Asub + m * 64 + kf * 4) = v;
        }
        #pragma unroll
        for (int j = 0; j < 8; j++) {
            int idx = tid + j * 256;
            int n   = idx >> 4;
            int kf  = idx & 15;
            float4 v = *(const float4*)(W + (size_t)(n0 + n) * 128 + k0 + kf * 4);
            Bsub[(kf * 4 + 0) * 130 + n] = v.x;
            Bsub[(kf * 4 + 1) * 130 + n] = v.y;
            Bsub[(kf * 4 + 2) * 130 + n] = v.z;
            Bsub[(kf * 4 + 3) * 130 + n] = v.w;
        }
        __syncthreads();

        #pragma unroll 4
        for (int k = 0; k < 64; k++) {
            unsigned long long a2[8];
            #pragma unroll
            for (int i = 0; i < 8; i++) {
                float a = Asub[(ty * 8 + i) * 64 + k];
                a2[i] = pack2(a, a);
            }
            unsigned long long b2[4];
            #pragma unroll
            for (int j = 0; j < 4; j++)
                b2[j] = *(const unsigned long long*)(Bsub + k * 130 + tx * 2 + j * 32);
            #pragma unroll
            for (int i = 0; i < 8; i++)
                #pragma unroll
                for (int j = 0; j < 4; j++)
                    fma2(acc[i][j], a2[i], b2[j]);
        }
        __syncthreads();
    }

    float2 bias[4];
    #pragma unroll
    for (int j = 0; j < 4; j++) {
        int n = n0 + tx * 2 + j * 32;
        bias[j].x = b_ih[n] + b_hh[n];
        bias[j].y = b_ih[n + 1] + b_hh[n + 1];
    }
    #pragma unroll
    for (int i = 0; i < 8; i++) {
        size_t m = m0 + ty * 8 + i;
        #pragma unroll
        for (int j = 0; j < 4; j++) {
            float x, y;
            unpack2(acc[i][j], x, y);
            __half2 hv = __floats2half2_rn(x + bias[j].x, y + bias[j].y);
            *(__half2*)(g_gxh + m * G4 + n0 + tx * 2 + j * 32) = hv;
        }
    }
}

// ---------------------------------------------------------------------------
// Transpose g_gxh [t][row][gate] -> g_gxt [t][cta][tid][8 halves]
// matching the MMA D-fragment order consumed by lstm_mma.
// grid (T_STEPS, NCTA), 512 threads; 8KB staging smem.
// ---------------------------------------------------------------------------
__global__ void __launch_bounds__(512)
transpose_gx() {
    __shared__ __half s[8 * 512];          // [row 8][gate 512]
    const int t   = blockIdx.x;
    const int c   = blockIdx.y;
    const int tid = threadIdx.x;
    const int w   = tid >> 5;
    const int l   = tid & 31;

    // coalesced load of 8 rows x 512 gates (contiguous 8KB)
    const uint4* src = (const uint4*)(g_gxh + ((size_t)t * BATCH + c * RPB) * G4);
    ((uint4*)s)[tid] = src[tid];
    __syncthreads();

    // gather this lstm-thread's 8 fragment values
    // j = mt*4 + reg: gate = (2*mt + (reg>>1))*128 + 8*w + (l>>2)
    //                 row  = 2*(l&3) + (reg&1)
    unsigned short h8[8];
    #pragma unroll
    for (int j = 0; j < 8; j++) {
        int mt  = j >> 2, reg = j & 3;
        int gate = (2 * mt + (reg >> 1)) * 128 + 8 * w + (l >> 2);
        int row  = 2 * (l & 3) + (reg & 1);
        h8[j] = __half_as_ushort(s[row * 512 + gate]);
    }
    uint4 o;
    o.x = (uint32_t)h8[0] | ((uint32_t)h8[1] << 16);
    o.y = (uint32_t)h8[2] | ((uint32_t)h8[3] << 16);
    o.z = (uint32_t)h8[4] | ((uint32_t)h8[5] << 16);
    o.w = (uint32_t)h8[6] | ((uint32_t)h8[7] << 16);
    ((uint4*)(g_gxt + (((size_t)t * NCTA + c) * TCN + tid) * 8))[0] = o;
}

// ---------------------------------------------------------------------------
// mma.sync LSTM recurrence.  128 CTAs x 512 threads (16 warps); 8 rows/CTA.
//
// Warp w owns 32 PERMUTED W rows = 2 m-tiles:
//   mtile mt rows r(0..15): gate type = 2*mt + r/8, unit = 8*w + r%8
// => thread (w,l)'s D fragments hold i,f,g,o for unit 8w+l/4, rows 2(l&3)+{0,1}.
// W fragments ldmatrix'd ONCE into 64 regs, reused all 640 steps.
// h double-buffered fp16 [8 n][136 k]; B frags via ldmatrix.x2; 1 bar/step.
// Future: W fragments reloaded with W_eff; W_lin m-tile on warps 0-7 -> out.
// ---------------------------------------------------------------------------
#define AB_OFF 0
#define AB_SZ  (512 * 136 * 2)                 // 139264
#define WL_OFF AB_SZ
#define WL_SZ  (128 * 136 * 2)                 // 34816
#define HB_OFF (AB_SZ + WL_SZ)                 // 174080
#define HB_SZ  (2 * 8 * 136 * 2)               // 4352
#define LSTM_SMEM (HB_OFF + HB_SZ)             // 178432
#define HROW   136                             // padded k per h row (halves)

__global__ void __launch_bounds__(TCN, 1)
lstm_mma(const float* __restrict__ W_lin, const float* __restrict__ b_lin,
         float* __restrict__ out) {
    extern __shared__ char smraw[];
    char* sm = smraw;
    const uint32_t smb = smem_u32(sm);

    const int tid = threadIdx.x;
    const int w   = tid >> 5;
    const int l   = tid & 31;
    const int c   = blockIdx.x;
    const int b0  = c * RPB;

    // ---- stage W_hh (permuted rows) into Abuf ----
    {
        const __half2* wsrc = (const __half2*)g_whh_h;
        for (int i = tid; i < 512 * 64; i += TCN) {
            int ma = i >> 6, kk = i & 63;
            int ww = ma >> 5, rem = ma & 31, mt = rem >> 4, r = rem & 15;
            int grow = (2 * mt + (r >> 3)) * 128 + 8 * ww + (r & 7);
            *(__half2*)(sm + AB_OFF + (ma * HROW + 2 * kk) * 2) = wsrc[grow * 64 + kk];
        }
    }
    // W_lin rows (canonical order) fp32 -> fp16
    for (int i = tid; i < 128 * 64; i += TCN) {
        int m = i >> 6, kk = i & 63;
        float2 wv = *(const float2*)(W_lin + m * 128 + 2 * kk);
        *(__half2*)(sm + WL_OFF + (m * HROW + 2 * kk) * 2) = __floats2half2_rn(wv.x, wv.y);
    }
    // zero both h buffers
    for (int i = tid; i < HB_SZ / 4; i += TCN)
        ((uint32_t*)(sm + HB_OFF))[i] = 0;
    __syncthreads();

    // ---- load W fragments into registers (held for the whole scan) ----
    uint32_t wf[2][8][4];
    {
        int arow_base = 32 * w + (l & 15);
        int acol = (l >> 4) * 8;
        #pragma unroll
        for (int mt = 0; mt < 2; mt++)
            #pragma unroll
            for (int ks = 0; ks < 8; ks++)
                ldsm_x4(wf[mt][ks],
                        smb + AB_OFF + ((arow_base + 16 * mt) * HROW + ks * 16 + acol) * 2);
    }

    // per-thread identity
    const int uu   = 8 * w + (l >> 2);       // unit
    const int r0   = 2 * (l & 3);            // first batch row
    // B ldmatrix address pieces
    const int bl   = l & 15;
    const int brow = bl & 7;
    const int bk8  = (bl >> 3) * 8;
    // h store half-offsets
    const int hst0 = r0 * HROW + uu;
    const int hst1 = hst0 + HROW;

    // prefetch gx for t=0
    uint4 gxc = ((const uint4*)(g_gxt + (((size_t)0 * NCTA + c) * TCN + tid) * 8))[0];

    float c0 = 0.0f, c1 = 0.0f;

    // ================= main scan =================
    for (int t = 0; t < T_STEPS; t++) {
        const uint32_t hb_rd = smb + HB_OFF + (((t & 1) ^ 1) ? HROW * 8 * 2 : 0);
        const uint32_t hb_wr_off = HB_OFF + ((t & 1) ? HROW * 8 * 2 : 0);

        float acc0[4], acc1[4];
        {
            float2 f0 = u2f2(gxc.x), f1 = u2f2(gxc.y);
            float2 f2 = u2f2(gxc.z), f3 = u2f2(gxc.w);
            acc0[0] = f0.x; acc0[1] = f0.y; acc0[2] = f1.x; acc0[3] = f1.y;
            acc1[0] = f2.x; acc1[1] = f2.y; acc1[2] = f3.x; acc1[3] = f3.y;
        }
        if (t + 1 < T_STEPS)
            gxc = ((const uint4*)(g_gxt + (((size_t)(t + 1) * NCTA + c) * TCN + tid) * 8))[0];

        #pragma unroll
        for (int ks = 0; ks < 8; ks++) {
            uint32_t bf[2];
            ldsm_x2(bf, hb_rd + (brow * HROW + ks * 16 + bk8) * 2);
            mma16816(acc0, wf[0][ks], bf);
            mma16816(acc1, wf[1][ks], bf);
        }

        // cells: acc0 = {i(r0), i(r1), f(r0), f(r1)}, acc1 = {g.., o..}
        c0 = fmaf(siga(acc0[2]), c0, siga(acc0[0]) * tanha(acc1[0]));
        float h0 = siga(acc1[2]) * tanha(c0);
        c1 = fmaf(siga(acc0[3]), c1, siga(acc0[1]) * tanha(acc1[1]));
        float h1 = siga(acc1[3]) * tanha(c1);

        *(__half*)(sm + hb_wr_off + hst0 * 2) = __float2half(h0);
        *(__half*)(sm + hb_wr_off + hst1 * 2) = __float2half(h1);
        __syncthreads();
    }

    // ---- reload W fragments with W_eff; fetch future constants ----
    {
        const __half2* esrc = (const __half2*)g_weff_h;
        for (int i = tid; i < 512 * 64; i += TCN) {
            int ma = i >> 6, kk = i & 63;
            int ww = ma >> 5, rem = ma & 31, mt = rem >> 4, r = rem & 15;
            int grow = (2 * mt + (r >> 3)) * 128 + 8 * ww + (r & 7);
            *(__half2*)(sm + AB_OFF + (ma * HROW + 2 * kk) * 2) = esrc[grow * 64 + kk];
        }
    }
    float bi = g_beff[0 * 128 + uu], bfo = g_beff[1 * 128 + uu];
    float bg = g_beff[2 * 128 + uu], bo = g_beff[3 * 128 + uu];
    float blin0 = 0.0f, blin1 = 0.0f;
    int uo0 = 0, uo1 = 0;
    if (w < 8) {
        uo0 = 16 * w + (l >> 2);
        uo1 = uo0 + 8;
        blin0 = b_lin[uo0];
        blin1 = b_lin[uo1];
    }
    __syncthreads();
    {
        int arow_base = 32 * w + (l & 15);
        int acol = (l >> 4) * 8;
        #pragma unroll
        for (int mt = 0; mt < 2; mt++)
            #pragma unroll
            for (int ks = 0; ks < 8; ks++)
                ldsm_x4(wf[mt][ks],
                        smb + AB_OFF + ((arow_base + 16 * mt) * HROW + ks * 16 + acol) * 2);
    }

    // ================= future phase (emits out[0..FUT]) =================
    const int wlrow = 16 * w + (l & 15);       // valid for w<8
    const int wlcol = (l >> 4) * 8;
    for (int ft = 0; ft <= FUT; ft++) {
        const int s = T_STEPS + ft;
        const uint32_t hb_rd = smb + HB_OFF + (((s & 1) ^ 1) ? HROW * 8 * 2 : 0);
        const uint32_t hb_wr_off = HB_OFF + ((s & 1) ? HROW * 8 * 2 : 0);
        const bool upd = (ft < FUT);

        float accO[4] = {blin0, blin0, blin1, blin1};
        float acc0[4] = {bi, bi, bfo, bfo};
        float acc1[4] = {bg, bg, bo, bo};

        #pragma unroll
        for (int ks = 0; ks < 8; ks++) {
            uint32_t bf[2];
            ldsm_x2(bf, hb_rd + (brow * HROW + ks * 16 + bk8) * 2);
            if (w < 8) {
                uint32_t wlf[4];
                ldsm_x4(wlf, smb + WL_OFF + (wlrow * HROW + ks * 16 + wlcol) * 2);
                mma16816(accO, wlf, bf);
            }
            if (upd) {
                mma16816(acc0, wf[0][ks], bf);
                mma16816(acc1, wf[1][ks], bf);
            }
        }

        if (w < 8) {
            float* op = out + (size_t)ft * BATCH * HID;
            op[(size_t)(b0 + r0)     * HID + uo0] = accO[0];
            op[(size_t)(b0 + r0 + 1) * HID + uo0] = accO[1];
            op[(size_t)(b0 + r0)     * HID + uo1] = accO[2];
            op[(size_t)(b0 + r0 + 1) * HID + uo1] = accO[3];
        }

        if (upd) {
            c0 = fmaf(siga(acc0[2]), c0, siga(acc0[0]) * tanha(acc1[0]));
            float h0 = siga(acc1[2]) * tanha(c0);
            c1 = fmaf(siga(acc0[3]), c1, siga(acc0[1]) * tanha(acc1[1]));
            float h1 = siga(acc1[3]) * tanha(c1);
            *(__half*)(sm + hb_wr_off + hst0 * 2) = __float2half(h0);
            *(__half*)(sm + hb_wr_off + hst1 * 2) = __float2half(h1);
            __syncthreads();
        }
    }
}

// ---------------------------------------------------------------------------
// Launch
// ---------------------------------------------------------------------------
extern "C" void kernel_launch(void* const* d_in, const int* in_sizes, int n_in,
                              void* d_out, int out_size) {
    const float* inp   = (const float*)d_in[0];   // [512,1024,128]
    const float* W_ih  = (const float*)d_in[1];   // [512,128]
    const float* W_hh  = (const float*)d_in[2];   // [512,128]
    const float* b_ih  = (const float*)d_in[3];   // [512]
    const float* b_hh  = (const float*)d_in[4];   // [512]
    const float* W_lin = (const float*)d_in[5];   // [128,128]
    const float* b_lin = (const float*)d_in[6];   // [128]
    float* out = (float*)d_out;                   // [129,1024,128]

    (void)in_sizes; (void)n_in; (void)out_size;

    cudaFuncSetAttribute(xgemm_kernel, cudaFuncAttributeMaxDynamicSharedMemorySize,
                         XGEMM_SMEM);
    cudaFuncSetAttribute(lstm_mma, cudaFuncAttributeMaxDynamicSharedMemorySize,
                         LSTM_SMEM);

    setup_kernel<<<256, 256>>>(W_ih, W_hh, b_ih, b_hh, W_lin, b_lin);
    xgemm_kernel<<<dim3(4096, 4), 256, XGEMM_SMEM>>>(inp, W_ih, b_ih, b_hh);
    transpose_gx<<<dim3(T_STEPS, NCTA), 512>>>();
    lstm_mma<<<NCTA, TCN, LSTM_SMEM>>>(W_lin, b_lin, out);
}

// round 12
// speedup vs baseline: 8.0728x; 3.3862x over previous
#include <cuda_runtime.h>
#include <cuda_fp16.h>
#include <cstdint>

// Problem dims (fixed by the dataset)
#define T_STEPS 512
#define BATCH   1024
#define DIM     128
#define HID     128
#define G4      512        // 4*HID
#define FUT     128

// recurrence config: 128 CTAs x 512 threads (16 warps), 8 batch rows / CTA
#define RPB   8                    // rows per block (MMA N)
#define NCTA  (BATCH / RPB)        // 128
#define TCN   512                  // threads
#define HROW  136                  // padded k per smem row (halves)

// xgemm_frag config
#define TGROUPS 8
#define TCHUNK  (T_STEPS / TGROUPS)   // 64

// ---------------------------------------------------------------------------
// Device scratch (allocation-free rule: static __device__ globals)
// ---------------------------------------------------------------------------
__device__ __half g_gxt[(size_t)T_STEPS * BATCH * G4];  // fragment-ordered x-gates: [t][cta][tid][8]
__device__ __half g_whh_h[G4 * HID];                    // fp16 W_hh (canonical)
__device__ __half g_weff_h[G4 * HID];                   // fp16 W_eff = W_hh + W_ih@W_lin
__device__ float  g_beff[G4];                           // b_eff = b_ih+b_hh + W_ih@b_lin

// ---------------------------------------------------------------------------
// helpers
// ---------------------------------------------------------------------------
__device__ __forceinline__ float tanha(float x) {
    float r; asm("tanh.approx.f32 %0, %1;" : "=f"(r) : "f"(x)); return r;
}
__device__ __forceinline__ float siga(float x) {      // sigmoid via tanh (1 MUFU)
    return fmaf(tanha(0.5f * x), 0.5f, 0.5f);
}
__device__ __forceinline__ uint32_t smem_u32(const void* p) {
    uint32_t a;
    asm("{ .reg .u64 t; cvta.to.shared.u64 t, %1; cvt.u32.u64 %0, t; }" : "=r"(a) : "l"(p));
    return a;
}
__device__ __forceinline__ float2 u2f2(uint32_t w) {
    __half2 h = *reinterpret_cast<__half2*>(&w);
    return __half22float2(h);
}
__device__ __forceinline__ uint32_t f2u2(float x, float y) {
    __half2 h = __floats2half2_rn(x, y);
    return *reinterpret_cast<uint32_t*>(&h);
}

// mma.sync m16n8k16 f16*f16->f32 accumulate in place
__device__ __forceinline__ void mma16816(float* d, const uint32_t* a, const uint32_t* b) {
    asm volatile(
        "mma.sync.aligned.m16n8k16.row.col.f32.f16.f16.f32 "
        "{%0,%1,%2,%3}, {%4,%5,%6,%7}, {%8,%9}, {%0,%1,%2,%3};"
        : "+f"(d[0]), "+f"(d[1]), "+f"(d[2]), "+f"(d[3])
        : "r"(a[0]), "r"(a[1]), "r"(a[2]), "r"(a[3]), "r"(b[0]), "r"(b[1]));
}
__device__ __forceinline__ void ldsm_x4(uint32_t* r, uint32_t addr) {
    asm volatile("ldmatrix.sync.aligned.m8n8.x4.shared.b16 {%0,%1,%2,%3}, [%4];"
        : "=r"(r[0]), "=r"(r[1]), "=r"(r[2]), "=r"(r[3]) : "r"(addr));
}
__device__ __forceinline__ void ldsm_x2(uint32_t* r, uint32_t addr) {
    asm volatile("ldmatrix.sync.aligned.m8n8.x2.shared.b16 {%0,%1}, [%2];"
        : "=r"(r[0]), "=r"(r[1]) : "r"(addr));
}

// ---------------------------------------------------------------------------
// Setup: W_eff, b_eff, fp16 copies.  65536 threads.
// ---------------------------------------------------------------------------
__global__ void setup_kernel(const float* __restrict__ W_ih,
                             const float* __restrict__ W_hh,
                             const float* __restrict__ b_ih,
                             const float* __restrict__ b_hh,
                             const float* __restrict__ W_lin,
                             const float* __restrict__ b_lin) {
    int idx = blockIdx.x * blockDim.x + threadIdx.x;   // 0 .. 65535
    int g = idx >> 7;
    int k = idx & 127;
    float s = W_hh[g * HID + k];
    #pragma unroll 8
    for (int j = 0; j < DIM; j++)
        s = fmaf(W_ih[g * DIM + j], W_lin[j * HID + k], s);
    g_weff_h[idx] = __float2half(s);
    g_whh_h[idx]  = __float2half(W_hh[idx]);
    if (idx < G4) {
        float b = b_ih[idx] + b_hh[idx];
        #pragma unroll 8
        for (int j = 0; j < DIM; j++)
            b = fmaf(W_ih[idx * DIM + j], b_lin[j], b);
        g_beff[idx] = b;
    }
}

// ---------------------------------------------------------------------------
// xgemm_frag: g_gxt[t][c][tid][8] = fragments of (inp[t] @ W_ih^T + bias)
//
// Same warp->gate mapping as lstm_mma: warp w owns 2 m-tiles of permuted
// W_ih rows; thread (w,l) emits i,f,g,o for unit 8w+l/4, rows 2(l&3)+{0,1}
// == exactly the uint4 the lstm kernel prefetches.  W_ih fragments live in
// registers for all TCHUNK steps; x double-buffered fp32->fp16 in smem.
// grid (NCTA, TGROUPS) x 512 threads.
// ---------------------------------------------------------------------------
#define XF_AB_SZ  (512 * HROW * 2)            // 139264
#define XF_XB_OFF XF_AB_SZ
#define XF_XBUF   (RPB * HROW * 2)            // 2176
#define XF_SMEM   (XF_XB_OFF + 2 * XF_XBUF)   // 143616

__global__ void __launch_bounds__(TCN, 1)
xgemm_frag(const float* __restrict__ inp, const float* __restrict__ W_ih,
           const float* __restrict__ b_ih, const float* __restrict__ b_hh) {
    extern __shared__ char smraw[];
    char* sm = smraw;
    const uint32_t smb = smem_u32(sm);

    const int tid = threadIdx.x;
    const int w   = tid >> 5;
    const int l   = tid & 31;
    const int c   = blockIdx.x;
    const int t0  = blockIdx.y * TCHUNK;

    // stage permuted W_ih (fp32 -> fp16)
    for (int i = tid; i < 512 * 64; i += TCN) {
        int ma = i >> 6, kk = i & 63;
        int ww = ma >> 5, rem = ma & 31, mt = rem >> 4, r = rem & 15;
        int grow = (2 * mt + (r >> 3)) * 128 + 8 * ww + (r & 7);
        float2 wv = *(const float2*)(W_ih + grow * 128 + 2 * kk);
        *(__half2*)(sm + (ma * HROW + 2 * kk) * 2) = __floats2half2_rn(wv.x, wv.y);
    }
    __syncthreads();

    // W_ih fragments -> registers
    uint32_t wf[2][8][4];
    {
        int arow = 32 * w + (l & 15);
        int acol = (l >> 4) * 8;
        #pragma unroll
        for (int mt = 0; mt < 2; mt++)
            #pragma unroll
            for (int ks = 0; ks < 8; ks++)
                ldsm_x4(wf[mt][ks], smb + ((arow + 16 * mt) * HROW + ks * 16 + acol) * 2);
    }

    // per-thread bias (gate order i,f,g,o for unit uu)
    const int uu = 8 * w + (l >> 2);
    const float bi_i = b_ih[          uu] + b_hh[          uu];
    const float bi_f = b_ih[128     + uu] + b_hh[128     + uu];
    const float bi_g = b_ih[256     + uu] + b_hh[256     + uu];
    const float bi_o = b_ih[384     + uu] + b_hh[384     + uu];

    // B ldmatrix address pieces
    const int bl   = l & 15;
    const int brow = bl & 7;
    const int bk8  = (bl >> 3) * 8;

    // x staging: thread -> (row tid>>6, dims (tid&63)*2 .. +1)
    const int xrow = tid >> 6;
    const int xcol = (tid & 63) * 2;
    const size_t xbase = (size_t)(c * RPB + xrow) * DIM + xcol;

    // preload t0 into buf 0
    {
        float2 xv = *(const float2*)(inp + (size_t)t0 * BATCH * DIM + xbase);
        *(__half2*)(sm + XF_XB_OFF + (xrow * HROW + xcol) * 2) =
            __floats2half2_rn(xv.x, xv.y);
    }
    __syncthreads();

    for (int ti = 0; ti < TCHUNK; ti++) {
        const int t = t0 + ti;
        const uint32_t rd = smb + XF_XB_OFF + ((ti & 1) ? XF_XBUF : 0);

        // prefetch next x (hidden under MMAs)
        float2 xn = make_float2(0.0f, 0.0f);
        if (ti + 1 < TCHUNK)
            xn = *(const float2*)(inp + (size_t)(t + 1) * BATCH * DIM + xbase);

        float acc0[4] = {bi_i, bi_i, bi_f, bi_f};
        float acc1[4] = {bi_g, bi_g, bi_o, bi_o};
        #pragma unroll
        for (int ks = 0; ks < 8; ks++) {
            uint32_t bf[2];
            ldsm_x2(bf, rd + (brow * HROW + ks * 16 + bk8) * 2);
            mma16816(acc0, wf[0][ks], bf);
            mma16816(acc1, wf[1][ks], bf);
        }

        // store next x to the other buffer (no conflict with reads of rd)
        if (ti + 1 < TCHUNK)
            *(__half2*)(sm + XF_XB_OFF + (((ti + 1) & 1) ? XF_XBUF : 0)
                        + (xrow * HROW + xcol) * 2) = __floats2half2_rn(xn.x, xn.y);

        // pack fragment -> fragment-ordered gmem (coalesced STG.128)
        uint4 o;
        o.x = f2u2(acc0[0], acc0[1]);
        o.y = f2u2(acc0[2], acc0[3]);
        o.z = f2u2(acc1[0], acc1[1]);
        o.w = f2u2(acc1[2], acc1[3]);
        ((uint4*)(g_gxt + (((size_t)t * NCTA + c) * TCN + tid) * 8))[0] = o;

        __syncthreads();
    }
}

// ---------------------------------------------------------------------------
// mma.sync LSTM recurrence.  128 CTAs x 512 threads (16 warps); 8 rows/CTA.
// (unchanged from round 8 — passed at 402us)
// ---------------------------------------------------------------------------
#define AB_OFF 0
#define AB_SZ  (512 * HROW * 2)                // 139264
#define WL_OFF AB_SZ
#define WL_SZ  (128 * HROW * 2)                // 34816
#define HB_OFF (AB_SZ + WL_SZ)                 // 174080
#define HB_SZ  (2 * 8 * HROW * 2)              // 4352
#define LSTM_SMEM (HB_OFF + HB_SZ)             // 178432

__global__ void __launch_bounds__(TCN, 1)
lstm_mma(const float* __restrict__ W_lin, const float* __restrict__ b_lin,
         float* __restrict__ out) {
    extern __shared__ char smraw[];
    char* sm = smraw;
    const uint32_t smb = smem_u32(sm);

    const int tid = threadIdx.x;
    const int w   = tid >> 5;
    const int l   = tid & 31;
    const int c   = blockIdx.x;
    const int b0  = c * RPB;

    // ---- stage W_hh (permuted rows) into Abuf ----
    {
        const __half2* wsrc = (const __half2*)g_whh_h;
        for (int i = tid; i < 512 * 64; i += TCN) {
            int ma = i >> 6, kk = i & 63;
            int ww = ma >> 5, rem = ma & 31, mt = rem >> 4, r = rem & 15;
            int grow = (2 * mt + (r >> 3)) * 128 + 8 * ww + (r & 7);
            *(__half2*)(sm + AB_OFF + (ma * HROW + 2 * kk) * 2) = wsrc[grow * 64 + kk];
        }
    }
    // W_lin rows (canonical order) fp32 -> fp16
    for (int i = tid; i < 128 * 64; i += TCN) {
        int m = i >> 6, kk = i & 63;
        float2 wv = *(const float2*)(W_lin + m * 128 + 2 * kk);
        *(__half2*)(sm + WL_OFF + (m * HROW + 2 * kk) * 2) = __floats2half2_rn(wv.x, wv.y);
    }
    // zero both h buffers
    for (int i = tid; i < HB_SZ / 4; i += TCN)
        ((uint32_t*)(sm + HB_OFF))[i] = 0;
    __syncthreads();

    // ---- load W fragments into registers (held for the whole scan) ----
    uint32_t wf[2][8][4];
    {
        int arow_base = 32 * w + (l & 15);
        int acol = (l >> 4) * 8;
        #pragma unroll
        for (int mt = 0; mt < 2; mt++)
            #pragma unroll
            for (int ks = 0; ks < 8; ks++)
                ldsm_x4(wf[mt][ks],
                        smb + AB_OFF + ((arow_base + 16 * mt) * HROW + ks * 16 + acol) * 2);
    }

    // per-thread identity
    const int uu   = 8 * w + (l >> 2);       // unit
    const int r0   = 2 * (l & 3);            // first batch row
    const int bl   = l & 15;
    const int brow = bl & 7;
    const int bk8  = (bl >> 3) * 8;
    const int hst0 = r0 * HROW + uu;
    const int hst1 = hst0 + HROW;

    // prefetch gx for t=0
    uint4 gxc = ((const uint4*)(g_gxt + (((size_t)0 * NCTA + c) * TCN + tid) * 8))[0];

    float c0 = 0.0f, c1 = 0.0f;

    // ================= main scan =================
    for (int t = 0; t < T_STEPS; t++) {
        const uint32_t hb_rd = smb + HB_OFF + (((t & 1) ^ 1) ? HROW * 8 * 2 : 0);
        const uint32_t hb_wr_off = HB_OFF + ((t & 1) ? HROW * 8 * 2 : 0);

        float acc0[4], acc1[4];
        {
            float2 f0 = u2f2(gxc.x), f1 = u2f2(gxc.y);
            float2 f2 = u2f2(gxc.z), f3 = u2f2(gxc.w);
            acc0[0] = f0.x; acc0[1] = f0.y; acc0[2] = f1.x; acc0[3] = f1.y;
            acc1[0] = f2.x; acc1[1] = f2.y; acc1[2] = f3.x; acc1[3] = f3.y;
        }
        if (t + 1 < T_STEPS)
            gxc = ((const uint4*)(g_gxt + (((size_t)(t + 1) * NCTA + c) * TCN + tid) * 8))[0];

        #pragma unroll
        for (int ks = 0; ks < 8; ks++) {
            uint32_t bf[2];
            ldsm_x2(bf, hb_rd + (brow * HROW + ks * 16 + bk8) * 2);
            mma16816(acc0, wf[0][ks], bf);
            mma16816(acc1, wf[1][ks], bf);
        }

        // cells: acc0 = {i(r0), i(r1), f(r0), f(r1)}, acc1 = {g.., o..}
        c0 = fmaf(siga(acc0[2]), c0, siga(acc0[0]) * tanha(acc1[0]));
        float h0 = siga(acc1[2]) * tanha(c0);
        c1 = fmaf(siga(acc0[3]), c1, siga(acc0[1]) * tanha(acc1[1]));
        float h1 = siga(acc1[3]) * tanha(c1);

        *(__half*)(sm + hb_wr_off + hst0 * 2) = __float2half(h0);
        *(__half*)(sm + hb_wr_off + hst1 * 2) = __float2half(h1);
        __syncthreads();
    }

    // ---- reload W fragments with W_eff; fetch future constants ----
    {
        const __half2* esrc = (const __half2*)g_weff_h;
        for (int i = tid; i < 512 * 64; i += TCN) {
            int ma = i >> 6, kk = i & 63;
            int ww = ma >> 5, rem = ma & 31, mt = rem >> 4, r = rem & 15;
            int grow = (2 * mt + (r >> 3)) * 128 + 8 * ww + (r & 7);
            *(__half2*)(sm + AB_OFF + (ma * HROW + 2 * kk) * 2) = esrc[grow * 64 + kk];
        }
    }
    float bi = g_beff[0 * 128 + uu], bfo = g_beff[1 * 128 + uu];
    float bg = g_beff[2 * 128 + uu], bo = g_beff[3 * 128 + uu];
    float blin0 = 0.0f, blin1 = 0.0f;
    int uo0 = 0, uo1 = 0;
    if (w < 8) {
        uo0 = 16 * w + (l >> 2);
        uo1 = uo0 + 8;
        blin0 = b_lin[uo0];
        blin1 = b_lin[uo1];
    }
    __syncthreads();
    {
        int arow_base = 32 * w + (l & 15);
        int acol = (l >> 4) * 8;
        #pragma unroll
        for (int mt = 0; mt < 2; mt++)
            #pragma unroll
            for (int ks = 0; ks < 8; ks++)
                ldsm_x4(wf[mt][ks],
                        smb + AB_OFF + ((arow_base + 16 * mt) * HROW + ks * 16 + acol) * 2);
    }

    // ================= future phase (emits out[0..FUT]) =================
    const int wlrow = 16 * w + (l & 15);       // valid for w<8
    const int wlcol = (l >> 4) * 8;
    for (int ft = 0; ft <= FUT; ft++) {
        const int s = T_STEPS + ft;
        const uint32_t hb_rd = smb + HB_OFF + (((s & 1) ^ 1) ? HROW * 8 * 2 : 0);
        const uint32_t hb_wr_off = HB_OFF + ((s & 1) ? HROW * 8 * 2 : 0);
        const bool upd = (ft < FUT);

        float accO[4] = {blin0, blin0, blin1, blin1};
        float acc0[4] = {bi, bi, bfo, bfo};
        float acc1[4] = {bg, bg, bo, bo};

        #pragma unroll
        for (int ks = 0; ks < 8; ks++) {
            uint32_t bf[2];
            ldsm_x2(bf, hb_rd + (brow * HROW + ks * 16 + bk8) * 2);
            if (w < 8) {
                uint32_t wlf[4];
                ldsm_x4(wlf, smb + WL_OFF + (wlrow * HROW + ks * 16 + wlcol) * 2);
                mma16816(accO, wlf, bf);
            }
            if (upd) {
                mma16816(acc0, wf[0][ks], bf);
                mma16816(acc1, wf[1][ks], bf);
            }
        }

        if (w < 8) {
            float* op = out + (size_t)ft * BATCH * HID;
            op[(size_t)(b0 + r0)     * HID + uo0] = accO[0];
            op[(size_t)(b0 + r0 + 1) * HID + uo0] = accO[1];
            op[(size_t)(b0 + r0)     * HID + uo1] = accO[2];
            op[(size_t)(b0 + r0 + 1) * HID + uo1] = accO[3];
        }

        if (upd) {
            c0 = fmaf(siga(acc0[2]), c0, siga(acc0[0]) * tanha(acc1[0]));
            float h0 = siga(acc1[2]) * tanha(c0);
            c1 = fmaf(siga(acc0[3]), c1, siga(acc0[1]) * tanha(acc1[1]));
            float h1 = siga(acc1[3]) * tanha(c1);
            *(__half*)(sm + hb_wr_off + hst0 * 2) = __float2half(h0);
            *(__half*)(sm + hb_wr_off + hst1 * 2) = __float2half(h1);
            __syncthreads();
        }
    }
}

// ---------------------------------------------------------------------------
// Launch
// ---------------------------------------------------------------------------
extern "C" void kernel_launch(void* const* d_in, const int* in_sizes, int n_in,
                              void* d_out, int out_size) {
    const float* inp   = (const float*)d_in[0];   // [512,1024,128]
    const float* W_ih  = (const float*)d_in[1];   // [512,128]
    const float* W_hh  = (const float*)d_in[2];   // [512,128]
    const float* b_ih  = (const float*)d_in[3];   // [512]
    const float* b_hh  = (const float*)d_in[4];   // [512]
    const float* W_lin = (const float*)d_in[5];   // [128,128]
    const float* b_lin = (const float*)d_in[6];   // [128]
    float* out = (float*)d_out;                   // [129,1024,128]

    (void)in_sizes; (void)n_in; (void)out_size;

    cudaFuncSetAttribute(xgemm_frag, cudaFuncAttributeMaxDynamicSharedMemorySize,
                         XF_SMEM);
    cudaFuncSetAttribute(lstm_mma, cudaFuncAttributeMaxDynamicSharedMemorySize,
                         LSTM_SMEM);

    setup_kernel<<<256, 256>>>(W_ih, W_hh, b_ih, b_hh, W_lin, b_lin);
    xgemm_frag<<<dim3(NCTA, TGROUPS), TCN, XF_SMEM>>>(inp, W_ih, b_ih, b_hh);
    lstm_mma<<<NCTA, TCN, LSTM_SMEM>>>(W_lin, b_lin, out);
}

// round 17
// speedup vs baseline: 8.7556x; 1.0846x over previous
#include <cuda_runtime.h>
#include <cuda_fp16.h>
#include <cstdint>

// Problem dims (fixed by the dataset)
#define T_STEPS 512
#define BATCH   1024
#define DIM     128
#define HID     128
#define G4      512        // 4*HID
#define FUT     128

// recurrence config: 128 CTAs x 512 threads (16 warps), 8 batch rows / CTA
#define RPB   8                    // rows per block (MMA N)
#define NCTA  (BATCH / RPB)        // 128
#define TCN   512                  // threads
#define HROW  136                  // padded k per smem row (halves)

// xgemm_frag config
#define TGROUPS 8
#define TCHUNK  (T_STEPS / TGROUPS)   // 64

// ---------------------------------------------------------------------------
// Device scratch (allocation-free rule: static __device__ globals)
// ---------------------------------------------------------------------------
__device__ __half g_gxt[(size_t)T_STEPS * BATCH * G4];  // fragment-ordered x-gates: [t][cta][tid][8]
__device__ __half g_whh_h[G4 * HID];                    // fp16 W_hh (canonical)
__device__ __half g_weff_h[G4 * HID];                   // fp16 W_eff = W_hh + W_ih@W_lin
__device__ float  g_beff[G4];                           // b_eff = b_ih+b_hh + W_ih@b_lin

// ---------------------------------------------------------------------------
// helpers
// ---------------------------------------------------------------------------
__device__ __forceinline__ float tanha(float x) {
    float r; asm("tanh.approx.f32 %0, %1;" : "=f"(r) : "f"(x)); return r;
}
__device__ __forceinline__ float siga(float x) {      // sigmoid via tanh (1 MUFU)
    return fmaf(tanha(0.5f * x), 0.5f, 0.5f);
}
__device__ __forceinline__ uint32_t smem_u32(const void* p) {
    uint32_t a;
    asm("{ .reg .u64 t; cvta.to.shared.u64 t, %1; cvt.u32.u64 %0, t; }" : "=r"(a) : "l"(p));
    return a;
}
__device__ __forceinline__ float2 u2f2(uint32_t w) {
    __half2 h = *reinterpret_cast<__half2*>(&w);
    return __half22float2(h);
}
__device__ __forceinline__ uint32_t f2u2(float x, float y) {
    __half2 h = __floats2half2_rn(x, y);
    return *reinterpret_cast<uint32_t*>(&h);
}

// mma.sync m16n8k16 f16*f16->f32 accumulate in place
__device__ __forceinline__ void mma16816(float* d, const uint32_t* a, const uint32_t* b) {
    asm volatile(
        "mma.sync.aligned.m16n8k16.row.col.f32.f16.f16.f32 "
        "{%0,%1,%2,%3}, {%4,%5,%6,%7}, {%8,%9}, {%0,%1,%2,%3};"
        : "+f"(d[0]), "+f"(d[1]), "+f"(d[2]), "+f"(d[3])
        : "r"(a[0]), "r"(a[1]), "r"(a[2]), "r"(a[3]), "r"(b[0]), "r"(b[1]));
}
__device__ __forceinline__ void ldsm_x4(uint32_t* r, uint32_t addr) {
    asm volatile("ldmatrix.sync.aligned.m8n8.x4.shared.b16 {%0,%1,%2,%3}, [%4];"
        : "=r"(r[0]), "=r"(r[1]), "=r"(r[2]), "=r"(r[3]) : "r"(addr));
}

// ---------------------------------------------------------------------------
// Dummy kernel (replicates R8 4-launch pattern so ncu captures lstm_mma)
// ---------------------------------------------------------------------------
__global__ void dummy_kernel() {}

// ---------------------------------------------------------------------------
// Setup: W_eff, b_eff, fp16 copies.  65536 threads.
// ---------------------------------------------------------------------------
__global__ void setup_kernel(const float* __restrict__ W_ih,
                             const float* __restrict__ W_hh,
                             const float* __restrict__ b_ih,
                             const float* __restrict__ b_hh,
                             const float* __restrict__ W_lin,
                             const float* __restrict__ b_lin) {
    int idx = blockIdx.x * blockDim.x + threadIdx.x;   // 0 .. 65535
    int g = idx >> 7;
    int k = idx & 127;
    float s = W_hh[g * HID + k];
    #pragma unroll 8
    for (int j = 0; j < DIM; j++)
        s = fmaf(W_ih[g * DIM + j], W_lin[j * HID + k], s);
    g_weff_h[idx] = __float2half(s);
    g_whh_h[idx]  = __float2half(W_hh[idx]);
    if (idx < G4) {
        float b = b_ih[idx] + b_hh[idx];
        #pragma unroll 8
        for (int j = 0; j < DIM; j++)
            b = fmaf(W_ih[idx * DIM + j], b_lin[j], b);
        g_beff[idx] = b;
    }
}

// ---------------------------------------------------------------------------
// xgemm_frag: g_gxt[t][c][tid][8] = fragments of (inp[t] @ W_ih^T + bias)
// 2 timesteps per iteration, 4-slot x ring, 1 __syncthreads per 2 steps.
// grid (NCTA, TGROUPS) x 512 threads.
// ---------------------------------------------------------------------------
#define XF_AB_SZ  (512 * HROW * 2)            // 139264
#define XF_XB_OFF XF_AB_SZ
#define XF_XBUF   (RPB * HROW * 2)            // 2176 per timestep slot
#define XF_SMEM   (XF_XB_OFF + 4 * XF_XBUF)   // 147968

__global__ void __launch_bounds__(TCN, 1)
xgemm_frag(const float* __restrict__ inp, const float* __restrict__ W_ih,
           const float* __restrict__ b_ih, const float* __restrict__ b_hh) {
    extern __shared__ char smraw[];
    char* sm = smraw;
    const uint32_t smb = smem_u32(sm);

    const int tid = threadIdx.x;
    const int w   = tid >> 5;
    const int l   = tid & 31;
    const int c   = blockIdx.x;
    const int t0  = blockIdx.y * TCHUNK;

    // stage permuted W_ih (fp32 -> fp16)
    for (int i = tid; i < 512 * 64; i += TCN) {
        int ma = i >> 6, kk = i & 63;
        int ww = ma >> 5, rem = ma & 31, mt = rem >> 4, r = rem & 15;
        int grow = (2 * mt + (r >> 3)) * 128 + 8 * ww + (r & 7);
        float2 wv = *(const float2*)(W_ih + grow * 128 + 2 * kk);
        *(__half2*)(sm + (ma * HROW + 2 * kk) * 2) = __floats2half2_rn(wv.x, wv.y);
    }
    __syncthreads();

    // W_ih fragments -> registers
    uint32_t wf[2][8][4];
    {
        int arow = 32 * w + (l & 15);
        int acol = (l >> 4) * 8;
        #pragma unroll
        for (int mt = 0; mt < 2; mt++)
            #pragma unroll
            for (int ks = 0; ks < 8; ks++)
                ldsm_x4(wf[mt][ks], smb + ((arow + 16 * mt) * HROW + ks * 16 + acol) * 2);
    }

    // per-thread bias (gate order i,f,g,o for unit uu)
    const int uu = 8 * w + (l >> 2);
    const float bi_i = b_ih[      uu] + b_hh[      uu];
    const float bi_f = b_ih[128 + uu] + b_hh[128 + uu];
    const float bi_g = b_ih[256 + uu] + b_hh[256 + uu];
    const float bi_o = b_ih[384 + uu] + b_hh[384 + uu];

    // B ldmatrix.x4 address pieces: lane -> (row l&7, k-half (l>>3)&1, ks-pair half l>>4)
    const uint32_t bB = (uint32_t)((l & 7) * HROW + ((l >> 3) & 1) * 8);
    const uint32_t bP = (uint32_t)((l >> 4) * 16);

    // x staging: thread -> (row tid>>6, dims (tid&63)*2 .. +1)
    const int xrow = tid >> 6;
    const int xcol = (tid & 63) * 2;
    const size_t xbase = (size_t)(c * RPB + xrow) * DIM + xcol;
    const uint32_t xsts = (uint32_t)((xrow * HROW + xcol) * 2);   // byte offset within a slot

    // preload t0 -> slot0, t0+1 -> slot1 (pair 0)
    {
        float2 x0 = *(const float2*)(inp + (size_t)t0 * BATCH * DIM + xbase);
        float2 x1 = *(const float2*)(inp + (size_t)(t0 + 1) * BATCH * DIM + xbase);
        *(__half2*)(sm + XF_XB_OFF + 0 * XF_XBUF + xsts) = __floats2half2_rn(x0.x, x0.y);
        *(__half2*)(sm + XF_XB_OFF + 1 * XF_XBUF + xsts) = __floats2half2_rn(x1.x, x1.y);
    }
    __syncthreads();

    #pragma unroll 2
    for (int j = 0; j < TCHUNK / 2; j++) {
        const int t = t0 + 2 * j;
        const uint32_t rdoff0 = XF_XB_OFF + ((j & 1) ? 2 : 0) * XF_XBUF;   // byte offsets
        const uint32_t rd0 = smb + rdoff0;
        const uint32_t rd1 = rd0 + XF_XBUF;
        const uint32_t wroff0 = XF_XB_OFF + ((j & 1) ? 0 : 2) * XF_XBUF;

        // prefetch next pair (hidden under MMAs)
        const bool pf = (2 * j + 2 < TCHUNK);
        float2 xn0 = make_float2(0.f, 0.f), xn1 = make_float2(0.f, 0.f);
        if (pf) {
            xn0 = *(const float2*)(inp + (size_t)(t + 2) * BATCH * DIM + xbase);
            xn1 = *(const float2*)(inp + (size_t)(t + 3) * BATCH * DIM + xbase);
        }

        // ---- step A ----
        {
            float acc0[4] = {bi_i, bi_i, bi_f, bi_f};
            float acc1[4] = {bi_g, bi_g, bi_o, bi_o};
            #pragma unroll
            for (int jp = 0; jp < 4; jp++) {
                uint32_t q[4];
                ldsm_x4(q, rd0 + (bB + 2 * jp * 16 + bP) * 2);
                mma16816(acc0, wf[0][2 * jp],     q);
                mma16816(acc1, wf[1][2 * jp],     q);
                mma16816(acc0, wf[0][2 * jp + 1], q + 2);
                mma16816(acc1, wf[1][2 * jp + 1], q + 2);
            }
            uint4 o;
            o.x = f2u2(acc0[0], acc0[1]);
            o.y = f2u2(acc0[2], acc0[3]);
            o.z = f2u2(acc1[0], acc1[1]);
            o.w = f2u2(acc1[2], acc1[3]);
            ((uint4*)(g_gxt + (((size_t)t * NCTA + c) * TCN + tid) * 8))[0] = o;
        }
        // ---- step B ----
        {
            float acc0[4] = {bi_i, bi_i, bi_f, bi_f};
            float acc1[4] = {bi_g, bi_g, bi_o, bi_o};
            #pragma unroll
            for (int jp = 0; jp < 4; jp++) {
                uint32_t q[4];
                ldsm_x4(q, rd1 + (bB + 2 * jp * 16 + bP) * 2);
                mma16816(acc0, wf[0][2 * jp],     q);
                mma16816(acc1, wf[1][2 * jp],     q);
                mma16816(acc0, wf[0][2 * jp + 1], q + 2);
                mma16816(acc1, wf[1][2 * jp + 1], q + 2);
            }
            uint4 o;
            o.x = f2u2(acc0[0], acc0[1]);
            o.y = f2u2(acc0[2], acc0[3]);
            o.z = f2u2(acc1[0], acc1[1]);
            o.w = f2u2(acc1[2], acc1[3]);
            ((uint4*)(g_gxt + (((size_t)(t + 1) * NCTA + c) * TCN + tid) * 8))[0] = o;
        }

        // store prefetched pair into the other slots (generic pointer, FIXED)
        if (pf) {
            *(__half2*)(sm + wroff0 + xsts)           = __floats2half2_rn(xn0.x, xn0.y);
            *(__half2*)(sm + wroff0 + XF_XBUF + xsts) = __floats2half2_rn(xn1.x, xn1.y);
        }
        __syncthreads();
    }
}

// ---------------------------------------------------------------------------
// mma.sync LSTM recurrence.  128 CTAs x 512 threads (16 warps); 8 rows/CTA.
// Split HMMA chains (depth 4 + 4, FADD join); B frags via ldmatrix.x4.
// ---------------------------------------------------------------------------
#define AB_OFF 0
#define AB_SZ  (512 * HROW * 2)                // 139264
#define WL_OFF AB_SZ
#define WL_SZ  (128 * HROW * 2)                // 34816
#define HB_OFF (AB_SZ + WL_SZ)                 // 174080
#define HB_SZ  (2 * 8 * HROW * 2)              // 4352
#define LSTM_SMEM (HB_OFF + HB_SZ)             // 178432

__global__ void __launch_bounds__(TCN, 1)
lstm_mma(const float* __restrict__ W_lin, const float* __restrict__ b_lin,
         float* __restrict__ out) {
    extern __shared__ char smraw[];
    char* sm = smraw;
    const uint32_t smb = smem_u32(sm);

    const int tid = threadIdx.x;
    const int w   = tid >> 5;
    const int l   = tid & 31;
    const int c   = blockIdx.x;
    const int b0  = c * RPB;

    // ---- stage W_hh (permuted rows) into Abuf ----
    {
        const __half2* wsrc = (const __half2*)g_whh_h;
        for (int i = tid; i < 512 * 64; i += TCN) {
            int ma = i >> 6, kk = i & 63;
            int ww = ma >> 5, rem = ma & 31, mt = rem >> 4, r = rem & 15;
            int grow = (2 * mt + (r >> 3)) * 128 + 8 * ww + (r & 7);
            *(__half2*)(sm + AB_OFF + (ma * HROW + 2 * kk) * 2) = wsrc[grow * 64 + kk];
        }
    }
    // W_lin rows (canonical order) fp32 -> fp16
    for (int i = tid; i < 128 * 64; i += TCN) {
        int m = i >> 6, kk = i & 63;
        float2 wv = *(const float2*)(W_lin + m * 128 + 2 * kk);
        *(__half2*)(sm + WL_OFF + (m * HROW + 2 * kk) * 2) = __floats2half2_rn(wv.x, wv.y);
    }
    // zero both h buffers
    for (int i = tid; i < HB_SZ / 4; i += TCN)
        ((uint32_t*)(sm + HB_OFF))[i] = 0;
    __syncthreads();

    // ---- load W fragments into registers (held for the whole scan) ----
    uint32_t wf[2][8][4];
    {
        int arow_base = 32 * w + (l & 15);
        int acol = (l >> 4) * 8;
        #pragma unroll
        for (int mt = 0; mt < 2; mt++)
            #pragma unroll
            for (int ks = 0; ks < 8; ks++)
                ldsm_x4(wf[mt][ks],
                        smb + AB_OFF + ((arow_base + 16 * mt) * HROW + ks * 16 + acol) * 2);
    }

    // per-thread identity
    const int uu   = 8 * w + (l >> 2);       // unit
    const int r0   = 2 * (l & 3);            // first batch row
    // B ldmatrix.x4 address pieces
    const uint32_t bB = (uint32_t)((l & 7) * HROW + ((l >> 3) & 1) * 8);
    const uint32_t bP = (uint32_t)((l >> 4) * 16);
    const int hst0 = r0 * HROW + uu;
    const int hst1 = hst0 + HROW;

    // prefetch gx for t=0
    uint4 gxc = ((const uint4*)(g_gxt + (((size_t)0 * NCTA + c) * TCN + tid) * 8))[0];

    float c0 = 0.0f, c1 = 0.0f;

    // ================= main scan =================
    for (int t = 0; t < T_STEPS; t++) {
        const uint32_t hb_rd = smb + HB_OFF + (((t & 1) ^ 1) ? HROW * 8 * 2 : 0);
        const uint32_t hb_wr_off = HB_OFF + ((t & 1) ? HROW * 8 * 2 : 0);

        // chain A seeded with gx, chain B zero; joined after the k loop
        float a0[4], a1[4];
        {
            float2 f0 = u2f2(gxc.x), f1 = u2f2(gxc.y);
            float2 f2 = u2f2(gxc.z), f3 = u2f2(gxc.w);
            a0[0] = f0.x; a0[1] = f0.y; a0[2] = f1.x; a0[3] = f1.y;
            a1[0] = f2.x; a1[1] = f2.y; a1[2] = f3.x; a1[3] = f3.y;
        }
        float e0[4] = {0.f, 0.f, 0.f, 0.f}, e1[4] = {0.f, 0.f, 0.f, 0.f};

        if (t + 1 < T_STEPS)
            gxc = ((const uint4*)(g_gxt + (((size_t)(t + 1) * NCTA + c) * TCN + tid) * 8))[0];

        #pragma unroll
        for (int jp = 0; jp < 4; jp++) {
            uint32_t q[4];
            ldsm_x4(q, hb_rd + (bB + 2 * jp * 16 + bP) * 2);
            // even ks -> chain A, odd ks -> chain B  (two independent 4-deep chains each)
            mma16816(a0, wf[0][2 * jp],     q);
            mma16816(a1, wf[1][2 * jp],     q);
            mma16816(e0, wf[0][2 * jp + 1], q + 2);
            mma16816(e1, wf[1][2 * jp + 1], q + 2);
        }
        float acc0[4], acc1[4];
        #pragma unroll
        for (int i = 0; i < 4; i++) { acc0[i] = a0[i] + e0[i]; acc1[i] = a1[i] + e1[i]; }

        // cells: acc0 = {i(r0), i(r1), f(r0), f(r1)}, acc1 = {g.., o..}
        c0 = fmaf(siga(acc0[2]), c0, siga(acc0[0]) * tanha(acc1[0]));
        float h0 = siga(acc1[2]) * tanha(c0);
        c1 = fmaf(siga(acc0[3]), c1, siga(acc0[1]) * tanha(acc1[1]));
        float h1 = siga(acc1[3]) * tanha(c1);

        *(__half*)(sm + hb_wr_off + hst0 * 2) = __float2half(h0);
        *(__half*)(sm + hb_wr_off + hst1 * 2) = __float2half(h1);
        __syncthreads();
    }

    // ---- reload W fragments with W_eff; fetch future constants ----
    {
        const __half2* esrc = (const __half2*)g_weff_h;
        for (int i = tid; i < 512 * 64; i += TCN) {
            int ma = i >> 6, kk = i & 63;
            int ww = ma >> 5, rem = ma & 31, mt = rem >> 4, r = rem & 15;
            int grow = (2 * mt + (r >> 3)) * 128 + 8 * ww + (r & 7);
            *(__half2*)(sm + AB_OFF + (ma * HROW + 2 * kk) * 2) = esrc[grow * 64 + kk];
        }
    }
    float bi = g_beff[0 * 128 + uu], bfo = g_beff[1 * 128 + uu];
    float bg = g_beff[2 * 128 + uu], bo = g_beff[3 * 128 + uu];
    float blin0 = 0.0f, blin1 = 0.0f;
    int uo0 = 0, uo1 = 0;
    if (w < 8) {
        uo0 = 16 * w + (l >> 2);
        uo1 = uo0 + 8;
        blin0 = b_lin[uo0];
        blin1 = b_lin[uo1];
    }
    __syncthreads();
    {
        int arow_base = 32 * w + (l & 15);
        int acol = (l >> 4) * 8;
        #pragma unroll
        for (int mt = 0; mt < 2; mt++)
            #pragma unroll
            for (int ks = 0; ks < 8; ks++)
                ldsm_x4(wf[mt][ks],
                        smb + AB_OFF + ((arow_base + 16 * mt) * HROW + ks * 16 + acol) * 2);
    }

    // ================= future phase (emits out[0..FUT]) =================
    const int wlrow = 16 * w + (l & 15);       // valid for w<8
    const int wlcol = (l >> 4) * 8;
    for (int ft = 0; ft <= FUT; ft++) {
        const int s = T_STEPS + ft;
        const uint32_t hb_rd = smb + HB_OFF + (((s & 1) ^ 1) ? HROW * 8 * 2 : 0);
        const uint32_t hb_wr_off = HB_OFF + ((s & 1) ? HROW * 8 * 2 : 0);
        const bool upd = (ft < FUT);

        float accO[4] = {blin0, blin0, blin1, blin1};
        float acc0[4] = {bi, bi, bfo, bfo};
        float acc1[4] = {bg, bg, bo, bo};

        #pragma unroll
        for (int jp = 0; jp < 4; jp++) {
            uint32_t q[4];
            ldsm_x4(q, hb_rd + (bB + 2 * jp * 16 + bP) * 2);
            if (w < 8) {
                uint32_t wlf[4];
                ldsm_x4(wlf, smb + WL_OFF + (wlrow * HROW + 2 * jp * 16 + wlcol) * 2);
                uint32_t wlf2[4];
                ldsm_x4(wlf2, smb + WL_OFF + (wlrow * HROW + (2 * jp + 1) * 16 + wlcol) * 2);
                mma16816(accO, wlf,  q);
                mma16816(accO, wlf2, q + 2);
            }
            if (upd) {
                mma16816(acc0, wf[0][2 * jp],     q);
                mma16816(acc1, wf[1][2 * jp],     q);
                mma16816(acc0, wf[0][2 * jp + 1], q + 2);
                mma16816(acc1, wf[1][2 * jp + 1], q + 2);
            }
        }

        if (w < 8) {
            float* op = out + (size_t)ft * BATCH * HID;
            op[(size_t)(b0 + r0)     * HID + uo0] = accO[0];
            op[(size_t)(b0 + r0 + 1) * HID + uo0] = accO[1];
            op[(size_t)(b0 + r0)     * HID + uo1] = accO[2];
            op[(size_t)(b0 + r0 + 1) * HID + uo1] = accO[3];
        }

        if (upd) {
            c0 = fmaf(siga(acc0[2]), c0, siga(acc0[0]) * tanha(acc1[0]));
            float h0 = siga(acc1[2]) * tanha(c0);
            c1 = fmaf(siga(acc0[3]), c1, siga(acc0[1]) * tanha(acc1[1]));
            float h1 = siga(acc1[3]) * tanha(c1);
            *(__half*)(sm + hb_wr_off + hst0 * 2) = __float2half(h0);
            *(__half*)(sm + hb_wr_off + hst1 * 2) = __float2half(h1);
            __syncthreads();
        }
    }
}

// ---------------------------------------------------------------------------
// Launch (4-launch pattern: setup, xgemm, dummy, lstm — ncu captured lstm
// with this shape in round 8)
// ---------------------------------------------------------------------------
extern "C" void kernel_launch(void* const* d_in, const int* in_sizes, int n_in,
                              void* d_out, int out_size) {
    const float* inp   = (const float*)d_in[0];   // [512,1024,128]
    const float* W_ih  = (const float*)d_in[1];   // [512,128]
    const float* W_hh  = (const float*)d_in[2];   // [512,128]
    const float* b_ih  = (const float*)d_in[3];   // [512]
    const float* b_hh  = (const float*)d_in[4];   // [512]
    const float* W_lin = (const float*)d_in[5];   // [128,128]
    const float* b_lin = (const float*)d_in[6];   // [128]
    float* out = (float*)d_out;                   // [129,1024,128]

    (void)in_sizes; (void)n_in; (void)out_size;

    cudaFuncSetAttribute(xgemm_frag, cudaFuncAttributeMaxDynamicSharedMemorySize,
                         XF_SMEM);
    cudaFuncSetAttribute(lstm_mma, cudaFuncAttributeMaxDynamicSharedMemorySize,
                         LSTM_SMEM);

    setup_kernel<<<256, 256>>>(W_ih, W_hh, b_ih, b_hh, W_lin, b_lin);
    xgemm_frag<<<dim3(NCTA, TGROUPS), TCN, XF_SMEM>>>(inp, W_ih, b_ih, b_hh);
    dummy_kernel<<<1, 32>>>();
    lstm_mma<<<NCTA, TCN, LSTM_SMEM>>>(W_lin, b_lin, out);
}